// round 13
// baseline (speedup 1.0000x reference)
#include <cuda_runtime.h>
#include <cuda_bf16.h>
#include <math.h>

typedef unsigned int u32;
typedef unsigned long long u64;

// ---------------- problem constants ----------------
#define NPIX    2500
#define HPAD    52
#define QPAD    2704          // 52*52
#define NCH     512
#define KTOT    4608          // 512*9
#define NA      35
#define NANCH   87500         // 2500*35
#define PRE_NMS 6000
#define POST_NMS 300
#define NW      94            // ceil(6000/64)
#define NTRI    (NW * (NW + 1) / 2)
#define TOPCAP  8192

// output layout (float32, concatenated tuple)
#define OFF_LOCS    0
#define OFF_SCORES  700000
#define OFF_ROIS    1050000
#define OFF_RIDX    1052400
#define OFF_RVALID  1053000
#define OFF_ANCH    1053600

// ---------------- device scratch (no allocation allowed) ----------------
__device__ __align__(16) float g_pad[2 * NCH * QPAD];
__device__ __align__(16) float g_h[2 * NCH * NPIX];
__device__ __align__(16) float g_scores[2 * 70 * NPIX];
__device__ __align__(16) float g_locs[2 * 140 * NPIX];
__device__ float4 g_anchors2[NANCH];     // a-major: [a][p]
__device__ u64    g_keys[2 * NANCH];
__device__ float4 g_boxes[2 * NANCH];
__device__ int    g_cnt[2];
__device__ u64    g_top[2 * TOPCAP];
__device__ float4 g_nmsbox[2 * PRE_NMS];
__device__ u64    g_mask[(size_t)2 * PRE_NMS * NW];
__device__ u64    g_validb[2 * NW];
__device__ u32    g_hist1[2 * 65536];
__device__ u32    g_hist2[2 * 65536];
__device__ u32    g_prefix[2];
__device__ u32    g_rank[2];
__device__ u32    g_thresh[2];

// ---------------- pad input (zero border) ----------------
__global__ void pad_kernel(const float* __restrict__ feat)
{
    int idx = blockIdx.x * blockDim.x + threadIdx.x;
    if (idx >= 2 * NCH * QPAD) return;
    int plane = idx / QPAD;
    int q = idx - plane * QPAD;
    int i = q / HPAD, j = q - i * HPAD;
    float v = 0.f;
    if (i >= 1 && i <= 50 && j >= 1 && j <= 50)
        v = feat[(size_t)plane * NPIX + (i - 1) * 50 + (j - 1)];
    g_pad[idx] = v;
}

// ---------------- zero counters + valid bits + histograms ----------------
__global__ void zero_kernel()
{
    int idx = blockIdx.x * blockDim.x + threadIdx.x;
    if (idx < 2) g_cnt[idx] = 0;
    if (idx < 2 * NW) g_validb[idx] = 0ull;
    if (idx < 2 * 65536) { g_hist1[idx] = 0; g_hist2[idx] = 0; }
}

// ---------------- anchors (fp64 base, fp32 add, clip) ----------------
__global__ void anchors_kernel(float* __restrict__ out)
{
    int idx = blockIdx.x * blockDim.x + threadIdx.x;
    if (idx >= NANCH) return;
    int p = idx / NA, a = idx - p * NA;
    int ri = a / 5, si = a - ri * 5;
    const double RAT[7] = {0.5, 0.66, 0.75, 1.0, 1.33, 1.5, 2.0};
    const double SCL[5] = {2.0, 4.0, 8.0, 16.0, 32.0};
    double hh = 16.0 * SCL[si] * sqrt(RAT[ri]);
    double ww = 16.0 * SCL[si] * sqrt(1.0 / RAT[ri]);
    float a0 = (float)(8.0 - hh / 2.0);
    float a1 = (float)(8.0 - ww / 2.0);
    float a2 = (float)(8.0 + hh / 2.0);
    float a3 = (float)(8.0 + ww / 2.0);
    int iy = p / 50, jx = p - iy * 50;
    float sy = (float)(iy * 16), sx = (float)(jx * 16);
    float y1 = fminf(fmaxf(a0 + sy, 0.f), 799.f);
    float x1 = fminf(fmaxf(a1 + sx, 0.f), 799.f);
    float y2 = fminf(fmaxf(a2 + sy, 0.f), 799.f);
    float x2 = fminf(fmaxf(a3 + sx, 0.f), 799.f);
    g_anchors2[a * NPIX + p] = make_float4(y1, x1, y2, x2);
    size_t o = OFF_ANCH + (size_t)idx * 4;
    out[o + 0] = y1; out[o + 1] = x1; out[o + 2] = y2; out[o + 3] = x2;
}

// ---------------- conv3x3 + bias + relu: 64co x 40pix tiles, 128 thr, occ-8 ----------------
// fine-grained block balance: 1008 blocks on 1184 occ-8 slots = single wave, 6-7 blocks/SM
#define PT2 40
__global__ void __launch_bounds__(128, 8)
conv3x3_kernel(const float* __restrict__ W, const float* __restrict__ bias)
{
    const int bx = blockIdx.x;      // pixel tile (63)
    const int by = blockIdx.y;      // co tile (8)
    const int bz = blockIdx.z;      // batch
    const int tid = threadIdx.x;
    const int n0 = bx * PT2;
    const int m0 = by * 64;
    __shared__ __align__(16) float As[2][8][64];
    __shared__ __align__(16) float Bs[2][8][PT2];
    const int tm = tid >> 3;        // 0..15 -> 4 co each
    const int tn = tid & 7;         // 0..7  -> 5 px each
    float acc[4][5];
#pragma unroll
    for (int u = 0; u < 4; u++)
#pragma unroll
        for (int v = 0; v < 5; v++) acc[u][v] = 0.f;

    const int a_co = tid >> 1;              // 0..63
    const int a_kq = (tid & 1) * 4;         // 0 / 4
    const int b_kk = tid >> 4;              // 0..7
    const int b_px = tid & 15;              // 0..15
    const float* padB = g_pad + (size_t)bz * NCH * QPAD;
    const float* wrow = W + (size_t)(m0 + a_co) * KTOT + a_kq;

    int poff[3];
    bool pok[3];
#pragma unroll
    for (int e = 0; e < 3; e++) {
        int px = b_px + e * 16;
        int p = n0 + px;
        pok[e] = (px < PT2) && (p < NPIX);
        int i = pok[e] ? (p / 50) : 0;
        int j = pok[e] ? (p - 50 * i) : 0;
        poff[e] = i * HPAD + j;
    }

    float4 av;
    float bv[3];
    {
        av = *(const float4*)&wrow[0];
        int k = b_kk;
        int ci = k / 9;
        int r = k - ci * 9;
        int dy = r / 3, dx = r - dy * 3;
        const float* pp = padB + (size_t)ci * QPAD + dy * HPAD + dx;
#pragma unroll
        for (int e = 0; e < 3; e++) bv[e] = pok[e] ? pp[poff[e]] : 0.f;
    }
    As[0][a_kq + 0][a_co] = av.x;
    As[0][a_kq + 1][a_co] = av.y;
    As[0][a_kq + 2][a_co] = av.z;
    As[0][a_kq + 3][a_co] = av.w;
#pragma unroll
    for (int e = 0; e < 3; e++) {
        int px = b_px + e * 16;
        if (px < PT2) Bs[0][b_kk][px] = bv[e];
    }
    __syncthreads();

    for (int k0 = 0; k0 < KTOT; k0 += 8) {
        int buf = (k0 >> 3) & 1;
        bool more = (k0 + 8 < KTOT);
        if (more) {
            av = *(const float4*)&wrow[k0 + 8];
            int k = k0 + 8 + b_kk;
            int ci = k / 9;
            int r = k - ci * 9;
            int dy = r / 3, dx = r - dy * 3;
            const float* pp = padB + (size_t)ci * QPAD + dy * HPAD + dx;
#pragma unroll
            for (int e = 0; e < 3; e++) bv[e] = pok[e] ? pp[poff[e]] : 0.f;
        }
#pragma unroll
        for (int kk = 0; kk < 8; kk++) {
            float4 aa = *(const float4*)&As[buf][kk][tm * 4];
            float aarr[4] = {aa.x, aa.y, aa.z, aa.w};
            float barr[5];
#pragma unroll
            for (int v = 0; v < 5; v++) barr[v] = Bs[buf][kk][tn * 5 + v];
#pragma unroll
            for (int u = 0; u < 4; u++)
#pragma unroll
                for (int v = 0; v < 5; v++)
                    acc[u][v] = fmaf(aarr[u], barr[v], acc[u][v]);
        }
        if (more) {
            int nb = buf ^ 1;
            As[nb][a_kq + 0][a_co] = av.x;
            As[nb][a_kq + 1][a_co] = av.y;
            As[nb][a_kq + 2][a_co] = av.z;
            As[nb][a_kq + 3][a_co] = av.w;
#pragma unroll
            for (int e = 0; e < 3; e++) {
                int px = b_px + e * 16;
                if (px < PT2) Bs[nb][b_kk][px] = bv[e];
            }
            __syncthreads();
        }
    }
#pragma unroll
    for (int u = 0; u < 4; u++) {
        int co = m0 + tm * 4 + u;
        float bb = bias[co];
        float* outrow = g_h + ((size_t)bz * NCH + co) * NPIX;
#pragma unroll
        for (int v = 0; v < 5; v++) {
            int p = n0 + tn * 5 + v;
            if (p < NPIX) outrow[p] = fmaxf(acc[u][v] + bb, 0.f);
        }
    }
}

// ---------------- 1x1 conv GEMM (scores + locs merged), double-buffered ----------------
__global__ void __launch_bounds__(256)
gemm1x1_kernel(const float* __restrict__ scorew, const float* __restrict__ scoreb,
               const float* __restrict__ locw, const float* __restrict__ locb)
{
    const int bx = blockIdx.x;
    const int byr = blockIdx.y;
    const int bz = blockIdx.z;
    const int tid = threadIdx.x;
    const float* W;
    const float* bias;
    float* outbase;
    int M, m0;
    if (byr < 2) { W = scorew; bias = scoreb; outbase = g_scores; M = 70; m0 = byr * 64; }
    else         { W = locw;   bias = locb;   outbase = g_locs;   M = 140; m0 = (byr - 2) * 64; }
    const int n0 = bx * 64;
    __shared__ __align__(16) float As[2][16][64];
    __shared__ __align__(16) float Bs[2][16][64];
    const int tm = tid >> 4, tn = tid & 15;
    float acc[4][4];
#pragma unroll
    for (int u = 0; u < 4; u++)
#pragma unroll
        for (int v = 0; v < 4; v++) acc[u][v] = 0.f;

    const int a_co = tid >> 2;
    const int a_kq = (tid & 3) * 4;
    const int b_kk = tid >> 4;
    const int b_p0 = (tid & 15) * 4;
    const float* Hb = g_h + (size_t)bz * NCH * NPIX;
    const int co = m0 + a_co;
    const int p0 = n0 + b_p0;
    const float4 z4 = make_float4(0.f, 0.f, 0.f, 0.f);

    float4 av = (co < M) ? *(const float4*)&W[(size_t)co * NCH + a_kq] : z4;
    float4 bv = (p0 < NPIX) ? *(const float4*)&Hb[(size_t)b_kk * NPIX + p0] : z4;
    As[0][a_kq + 0][a_co] = av.x;
    As[0][a_kq + 1][a_co] = av.y;
    As[0][a_kq + 2][a_co] = av.z;
    As[0][a_kq + 3][a_co] = av.w;
    *(float4*)&Bs[0][b_kk][b_p0] = bv;
    __syncthreads();

    for (int k0 = 0; k0 < NCH; k0 += 16) {
        int buf = (k0 >> 4) & 1;
        bool more = (k0 + 16 < NCH);
        if (more) {
            av = (co < M) ? *(const float4*)&W[(size_t)co * NCH + k0 + 16 + a_kq] : z4;
            bv = (p0 < NPIX) ? *(const float4*)&Hb[(size_t)(k0 + 16 + b_kk) * NPIX + p0] : z4;
        }
#pragma unroll
        for (int kk = 0; kk < 16; kk++) {
            float4 aa = *(const float4*)&As[buf][kk][tm * 4];
            float4 bb = *(const float4*)&Bs[buf][kk][tn * 4];
            float aarr[4] = {aa.x, aa.y, aa.z, aa.w};
            float barr[4] = {bb.x, bb.y, bb.z, bb.w};
#pragma unroll
            for (int u = 0; u < 4; u++)
#pragma unroll
                for (int v = 0; v < 4; v++)
                    acc[u][v] = fmaf(aarr[u], barr[v], acc[u][v]);
        }
        if (more) {
            int nb = buf ^ 1;
            As[nb][a_kq + 0][a_co] = av.x;
            As[nb][a_kq + 1][a_co] = av.y;
            As[nb][a_kq + 2][a_co] = av.z;
            As[nb][a_kq + 3][a_co] = av.w;
            *(float4*)&Bs[nb][b_kk][b_p0] = bv;
            __syncthreads();
        }
    }
#pragma unroll
    for (int u = 0; u < 4; u++) {
        int cu = m0 + tm * 4 + u;
        if (cu >= M) continue;
        float bb = bias[cu];
        float* orow = outbase + ((size_t)bz * M + cu) * NPIX;
#pragma unroll
        for (int v = 0; v < 4; v++) {
            int p = n0 + tn * 4 + v;
            if (p < NPIX) orow[p] = acc[u][v] + bb;
        }
    }
}

// ---------------- decode boxes + fused histogram pass 0 ----------------
__global__ void decode_kernel(float* __restrict__ out)
{
    __shared__ int sneg[2];
    if (threadIdx.x < 2) sneg[threadIdx.x] = 0;
    __syncthreads();

    int t = blockIdx.x * blockDim.x + threadIdx.x;
    int lane = threadIdx.x & 31;
    bool in = (t < 2 * NANCH);
    int b = 0;
    u32 bin = 0;
    if (in) {
        b = t / NANCH;
        int r = t - b * NANCH;
        int a = r / NPIX;
        int p = r - a * NPIX;
        int pa = p * NA + a;

        const float* sc = g_scores + (size_t)b * 70 * NPIX;
        float x0 = sc[(a * 2 + 0) * NPIX + p];
        float x1 = sc[(a * 2 + 1) * NPIX + p];
        size_t so = OFF_SCORES + (size_t)b * 175000 + (size_t)pa * 2;
        out[so + 0] = x0;
        out[so + 1] = x1;
        float mx = fmaxf(x0, x1);
        float e0 = expf(x0 - mx), e1 = expf(x1 - mx);
        float fg = e1 / (e0 + e1);

        const float* lc = g_locs + (size_t)b * 140 * NPIX;
        float dy  = lc[(a * 4 + 0) * NPIX + p];
        float dx_ = lc[(a * 4 + 1) * NPIX + p];
        float dh  = lc[(a * 4 + 2) * NPIX + p];
        float dw  = lc[(a * 4 + 3) * NPIX + p];
        size_t lo = OFF_LOCS + (size_t)b * 350000 + (size_t)pa * 4;
        out[lo + 0] = dy; out[lo + 1] = dx_; out[lo + 2] = dh; out[lo + 3] = dw;

        float4 an = g_anchors2[a * NPIX + p];
        float ah = an.z - an.x, aw = an.w - an.y;
        float acy = an.x + 0.5f * ah, acx = an.y + 0.5f * aw;
        float cy = dy * ah + acy, cx = dx_ * aw + acx;
        float hh = expf(dh) * ah, ww = expf(dw) * aw;
        float y1 = cy - 0.5f * hh, x1b = cx - 0.5f * ww;
        float y2 = cy + 0.5f * hh, x2b = cx + 0.5f * ww;
        y1 = fminf(fmaxf(y1, 0.f), 800.f);
        x1b = fminf(fmaxf(x1b, 0.f), 800.f);
        y2 = fminf(fmaxf(y2, 0.f), 800.f);
        x2b = fminf(fmaxf(x2b, 0.f), 800.f);
        float hs = y2 - y1, ws = x2b - x1b;
        bool valid = (hs >= 16.f) && (ws >= 16.f);
        float s = valid ? fg : -__int_as_float(0x7f800000);

        u32 sb = __float_as_uint(s);
        u32 mm = (sb & 0x80000000u) ? ~sb : (sb | 0x80000000u);
        u64 key = ((u64)(~mm) << 32) | (u32)pa;   // ascending key = best first
        g_keys[(size_t)b * NANCH + pa] = key;
        g_boxes[(size_t)b * NANCH + pa] = make_float4(y1, x1b, y2, x2b);
        bin = (u32)(key >> 48);
    }
    unsigned act = __ballot_sync(0xffffffffu, in);
    if (in) {
        u32 tag = (u32)b << 16 | bin;
        unsigned grp = __match_any_sync(act, tag);
        int leader = __ffs(grp) - 1;
        if (lane == leader) {
            if (bin == 0xFF80u) atomicAdd(&sneg[b], (int)__popc(grp));
            else                atomicAdd(&g_hist1[b * 65536 + bin], (u32)__popc(grp));
        }
    }
    __syncthreads();
    if (threadIdx.x < 2 && sneg[threadIdx.x] > 0)
        atomicAdd(&g_hist1[threadIdx.x * 65536 + 0xFF80], (u32)sneg[threadIdx.x]);
}

// ---------------- histogram pass 1 (16-bit digits, warp-aggregated atomics) ----------------
__global__ void hist_kernel()
{
    int idx = blockIdx.x * blockDim.x + threadIdx.x;
    int lane = threadIdx.x & 31;
    bool ok = (idx < 2 * NANCH);
    int b = 0;
    u32 bin = 0;
    if (ok) {
        b = idx / NANCH;
        u64 k = g_keys[idx];
        if ((u32)(k >> 48) == g_prefix[b]) bin = (u32)((k >> 32) & 0xffffu);
        else ok = false;
    }
    unsigned act = __ballot_sync(0xffffffffu, ok);
    if (ok) {
        u32 tag = (u32)b << 16 | bin;
        unsigned grp = __match_any_sync(act, tag);
        int leader = __ffs(grp) - 1;
        if (lane == leader)
            atomicAdd(&g_hist2[b * 65536 + bin], (u32)__popc(grp));
    }
}

// ---------------- scan 65536 bins, locate rank (uint4 loads) ----------------
__global__ void scan_kernel(int pass)
{
    int b = blockIdx.x;
    int tid = threadIdx.x;  // 1024
    const u32* base = (pass == 0 ? g_hist1 : g_hist2) + b * 65536;
    __shared__ u32 ssum[1024];
    u32 local = 0;
    const uint4* b4 = (const uint4*)(base + tid * 64);
#pragma unroll
    for (int j = 0; j < 16; j++) {
        uint4 v4 = b4[j];
        local += v4.x + v4.y + v4.z + v4.w;
    }
    ssum[tid] = local;
    __syncthreads();
    for (int off = 1; off < 1024; off <<= 1) {
        u32 v = (tid >= off) ? ssum[tid - off] : 0;
        __syncthreads();
        ssum[tid] += v;
        __syncthreads();
    }
    u32 incl = ssum[tid];
    u32 excl = incl - local;
    u32 rank = (pass == 0) ? (PRE_NMS - 1) : g_rank[b];
    if (excl <= rank && rank < incl) {
        u32 run = excl;
        for (int j = 0; j < 64; j++) {
            u32 c = base[tid * 64 + j];
            if (run + c > rank) {
                u32 digit = (u32)(tid * 64 + j);
                g_rank[b] = rank - run;
                if (pass == 0) g_prefix[b] = digit;
                else g_thresh[b] = (g_prefix[b] << 16) | digit;
                break;
            }
            run += c;
        }
    }
}

// ---------------- compact keys with score32 <= thresh (warp-aggregated, per-batch) ----------------
__global__ void compact_kernel()
{
    int idx = blockIdx.x * blockDim.x + threadIdx.x;
    int lane = threadIdx.x & 31;
    bool ok = false;
    int b = 0;
    u64 k = 0;
    if (idx < 2 * NANCH) {
        b = idx / NANCH;
        k = g_keys[idx];
        ok = ((u32)(k >> 32) <= g_thresh[b]);
    }
#pragma unroll
    for (int bb = 0; bb < 2; bb++) {
        unsigned m = __ballot_sync(0xffffffffu, ok && b == bb);
        if (m) {
            int leader = __ffs(m) - 1;
            int base = 0;
            if (lane == leader) base = atomicAdd(&g_cnt[bb], __popc(m));
            base = __shfl_sync(0xffffffffu, base, leader);
            if (ok && b == bb) {
                int pos = base + __popc(m & ((1u << lane) - 1));
                if (pos < TOPCAP) g_top[(size_t)bb * TOPCAP + pos] = k;
            }
        }
    }
}

// ---------------- bitonic sort, local phase: k=2..1024 within 1024-aligned runs ----------------
__global__ void __launch_bounds__(1024)
local_sort_kernel()
{
    __shared__ u64 s[1024];
    int m = blockIdx.x;       // 0..7
    int b = blockIdx.y;
    int lt = threadIdx.x;
    int base = m * 1024;
    int cnt = g_cnt[b];
    if (cnt > TOPCAP) cnt = TOPCAP;
    int gi = base + lt;
    s[lt] = (gi < cnt) ? g_top[(size_t)b * TOPCAP + gi] : ~0ull;
    __syncthreads();
    for (int k = 2; k <= 1024; k <<= 1) {
        for (int j = k >> 1; j > 0; j >>= 1) {
            int ixj = lt ^ j;
            if (ixj > lt) {
                bool up = (((base + lt) & k) == 0);
                u64 x = s[lt], y = s[ixj];
                if ((x > y) == up) { s[lt] = y; s[ixj] = x; }
            }
            __syncthreads();
        }
    }
    g_top[(size_t)b * TOPCAP + gi] = s[lt];
}

// ---------------- bitonic merge k=2048..8192 + fused gather epilogue ----------------
__global__ void __launch_bounds__(1024)
merge_gather_kernel()
{
    extern __shared__ u64 s[];
    int b = blockIdx.x;
    int tid = threadIdx.x;
    for (int i = tid; i < TOPCAP; i += 1024)
        s[i] = g_top[(size_t)b * TOPCAP + i];
    __syncthreads();
    for (int k = 2048; k <= TOPCAP; k <<= 1) {
        for (int j = k >> 1; j > 0; j >>= 1) {
            for (int t = tid; t < TOPCAP; t += 1024) {
                int ixj = t ^ j;
                if (ixj > t) {
                    bool up = ((t & k) == 0);
                    u64 x = s[t], y = s[ixj];
                    if ((x > y) == up) { s[t] = y; s[ixj] = x; }
                }
            }
            __syncthreads();
        }
    }
    for (int i = tid; i < PRE_NMS; i += 1024) {
        u64 k = s[i];
        u32 ai = (u32)(k & 0xffffffffull);
        g_nmsbox[(size_t)b * PRE_NMS + i] = g_boxes[(size_t)b * NANCH + ai];
        bool valid = ((u32)(k >> 32)) != 0xFF800000u;
        if (valid) atomicOr(&g_validb[b * NW + (i >> 6)], 1ull << (i & 63));
    }
}

// ---------------- NMS IoU bitmask (triangular grid) ----------------
__global__ void nms_mask_kernel()
{
    int t = blockIdx.x;
    int b = blockIdx.y;
    int rb = (int)((2.0 * NW + 1.0 - sqrt((2.0 * NW + 1.0) * (2.0 * NW + 1.0) - 8.0 * t)) * 0.5);
    if (rb < 0) rb = 0;
    if (rb > NW - 1) rb = NW - 1;
    while (rb > 0 && (rb * NW - rb * (rb - 1) / 2) > t) rb--;
    while (rb < NW - 1 && ((rb + 1) * NW - (rb + 1) * rb / 2) <= t) rb++;
    int cb = rb + (t - (rb * NW - rb * (rb - 1) / 2));

    int tid = threadIdx.x;
    __shared__ float4 cbox[64];
    int j = cb * 64 + tid;
    cbox[tid] = (j < PRE_NMS) ? g_nmsbox[(size_t)b * PRE_NMS + j]
                              : make_float4(0.f, 0.f, 0.f, 0.f);
    __syncthreads();
    int i = rb * 64 + tid;
    if (i >= PRE_NMS) return;
    float4 rr = g_nmsbox[(size_t)b * PRE_NMS + i];
    float areai = (rr.z - rr.x) * (rr.w - rr.y);
    u64 bits = 0ull;
    if (cb > rb) {
#pragma unroll 4
        for (int c = 0; c < 64; c++) {
            float4 cc = cbox[c];
            float ty = fmaxf(rr.x, cc.x), tx = fmaxf(rr.y, cc.y);
            float by = fminf(rr.z, cc.z), bx2 = fminf(rr.w, cc.w);
            float wy = fmaxf(by - ty, 0.f), wx = fmaxf(bx2 - tx, 0.f);
            float inter = wy * wx;
            float areaj = (cc.z - cc.x) * (cc.w - cc.y);
            float iou = inter / (areai + areaj - inter + 1e-9f);
            if (iou > 0.7f) bits |= 1ull << c;
        }
    } else {
        for (int c = tid + 1; c < 64; c++) {
            float4 cc = cbox[c];
            float ty = fmaxf(rr.x, cc.x), tx = fmaxf(rr.y, cc.y);
            float by = fminf(rr.z, cc.z), bx2 = fminf(rr.w, cc.w);
            float wy = fmaxf(by - ty, 0.f), wx = fmaxf(bx2 - tx, 0.f);
            float inter = wy * wx;
            float areaj = (cc.z - cc.x) * (cc.w - cc.y);
            float iou = inter / (areai + areaj - inter + 1e-9f);
            if (iou > 0.7f) bits |= 1ull << c;
        }
    }
    g_mask[((size_t)b * PRE_NMS + i) * NW + cb] = bits;
}

// ---------------- NMS reduction v5 + fused finalize ----------------
__global__ void __launch_bounds__(512)
nms_reduce_finalize_kernel(float* __restrict__ out)
{
    int b = blockIdx.x;
    int tid = threadIdx.x;
    __shared__ u64 diag[2][64];
    __shared__ u64 remv[NW];
    __shared__ u64 svalid[NW];
    __shared__ u64 kw[NW];
    __shared__ int klist[64];
    __shared__ int snk;
    for (int v = tid; v < NW; v += 512) {
        remv[v] = 0ull;
        svalid[v] = g_validb[b * NW + v];
    }
    if (tid < 64)
        diag[0][tid] = (tid < PRE_NMS) ? g_mask[((size_t)b * PRE_NMS + tid) * NW + 0] : 0ull;
    __syncthreads();

    for (int w = 0; w < NW; w++) {
        int buf = w & 1;
        u64 rv = 0ull;
        if (w + 1 < NW && tid < 64) {
            int i = (w + 1) * 64 + tid;
            if (i < PRE_NMS) rv = g_mask[((size_t)b * PRE_NMS + i) * NW + (w + 1)];
        }
        if (tid == 0) {
            u64 cur = svalid[w] & ~remv[w];
            u64 kp = 0ull;
            int nk = 0;
            while (cur) {
                int bit = __ffsll((long long)cur) - 1;
                kp |= (1ull << bit);
                klist[nk++] = w * 64 + bit;
                cur &= ~diag[buf][bit];
                cur &= ~(1ull << bit);
            }
            snk = nk;
            kw[w] = kp;
        }
        __syncthreads();
        if (w + 1 < NW && tid < 64) diag[buf ^ 1][tid] = rv;
        int nk = snk;
        if (nk > 0) {
            int nv = NW - 1 - w;
            int total = nk * nv;
            for (int e0 = tid; e0 < total; e0 += 4096) {
                u64 mv[8];
                int vv[8];
#pragma unroll
                for (int s2 = 0; s2 < 8; s2++) {
                    int e = e0 + s2 * 512;
                    mv[s2] = 0ull;
                    vv[s2] = w + 1;
                    if (e < total) {
                        int q = e / nv;
                        int v = w + 1 + (e - q * nv);
                        vv[s2] = v;
                        mv[s2] = g_mask[((size_t)b * PRE_NMS + klist[q]) * NW + v];
                    }
                }
#pragma unroll
                for (int s2 = 0; s2 < 8; s2++)
                    if (mv[s2]) atomicOr(&remv[vv[s2]], mv[s2]);
            }
        }
        __syncthreads();
    }

    // ---- fused finalize ----
    __shared__ u32 kscan[NW];
    __shared__ u32 ktot;
    __shared__ int sel[POST_NMS];
    if (tid == 0) {
        u32 r = 0;
        for (int w = 0; w < NW; w++) { kscan[w] = r; r += (u32)__popcll(kw[w]); }
        ktot = r;
    }
    __syncthreads();
    u32 ktot_l = ktot;
    for (int w = tid; w < NW; w += 512) {
        u64 bits = kw[w];
        u32 base = kscan[w];
        u64 t = bits;
        while (t) {
            int bit = __ffsll((long long)t) - 1;
            t &= t - 1;
            if (base < POST_NMS) sel[base] = w * 64 + bit;
            base++;
        }
        u64 lim = (w == NW - 1) ? ((1ull << 48) - 1ull) : ~0ull;  // 6000 = 93*64+48
        u64 nt = (~bits) & lim;
        while (nt) {
            int bit = __ffsll((long long)nt) - 1;
            nt &= nt - 1;
            int i = w * 64 + bit;
            u64 below = (bit == 0) ? 0ull : ((1ull << bit) - 1ull);
            u32 kept_before = kscan[w] + (u32)__popcll(bits & below);
            u32 slot = ktot_l + (u32)i - kept_before;
            if (slot < POST_NMS) sel[slot] = i;
        }
    }
    __syncthreads();
    for (int s2 = tid; s2 < POST_NMS; s2 += 512) {
        int i = sel[s2];
        int v = (int)((kw[i >> 6] >> (i & 63)) & 1ull);
        float4 bx = v ? g_nmsbox[(size_t)b * PRE_NMS + i] : make_float4(0.f, 0.f, 0.f, 0.f);
        size_t ro = OFF_ROIS + (size_t)b * POST_NMS * 4 + (size_t)s2 * 4;
        out[ro + 0] = bx.x; out[ro + 1] = bx.y; out[ro + 2] = bx.z; out[ro + 3] = bx.w;
        out[OFF_RIDX + (size_t)b * POST_NMS + s2] = (float)b;
        out[OFF_RVALID + (size_t)b * POST_NMS + s2] = (float)v;
    }
}

// ---------------- launch ----------------
extern "C" void kernel_launch(void* const* d_in, const int* in_sizes, int n_in,
                              void* d_out, int out_size)
{
    const float* feat   = (const float*)d_in[0];
    const float* convw  = (const float*)d_in[1];
    const float* convb  = (const float*)d_in[2];
    const float* scorew = (const float*)d_in[3];
    const float* scoreb = (const float*)d_in[4];
    const float* locw   = (const float*)d_in[5];
    const float* locb   = (const float*)d_in[6];
    float* out = (float*)d_out;

    cudaFuncSetAttribute(merge_gather_kernel, cudaFuncAttributeMaxDynamicSharedMemorySize, 65536);

    // profiled slot = index 3 -> new conv3x3
    pad_kernel<<<(2 * NCH * QPAD + 255) / 256, 256>>>(feat);                 // 0
    zero_kernel<<<(2 * 65536 + 255) / 256, 256>>>();                         // 1
    anchors_kernel<<<(NANCH + 127) / 128, 128>>>(out);                       // 2
    conv3x3_kernel<<<dim3(63, 8, 2), 128>>>(convw, convb);                   // 3  <- profiled
    gemm1x1_kernel<<<dim3(40, 5, 2), 256>>>(scorew, scoreb, locw, locb);     // 4
    decode_kernel<<<(2 * NANCH + 255) / 256, 256>>>(out);                    // 5
    scan_kernel<<<2, 1024>>>(0);                                             // 6
    hist_kernel<<<(2 * NANCH + 255) / 256, 256>>>();                         // 7
    scan_kernel<<<2, 1024>>>(1);                                             // 8
    compact_kernel<<<(2 * NANCH + 255) / 256, 256>>>();                      // 9
    local_sort_kernel<<<dim3(8, 2), 1024>>>();                               // 10
    merge_gather_kernel<<<2, 1024, 65536>>>();                               // 11
    nms_mask_kernel<<<dim3(NTRI, 2), 64>>>();                                // 12
    nms_reduce_finalize_kernel<<<2, 512>>>(out);                             // 13
}

// round 15
// speedup vs baseline: 1.1032x; 1.1032x over previous
#include <cuda_runtime.h>
#include <cuda_bf16.h>
#include <math.h>

typedef unsigned int u32;
typedef unsigned long long u64;

// ---------------- problem constants ----------------
#define NPIX    2500
#define HPAD    52
#define QPAD    2704          // 52*52
#define NCH     512
#define KTOT    4608          // 512*9
#define NA      35
#define NANCH   87500         // 2500*35
#define PRE_NMS 6000
#define POST_NMS 300
#define NW      94            // ceil(6000/64)
#define NTRI    (NW * (NW + 1) / 2)
#define TOPCAP  8192

// output layout (float32, concatenated tuple)
#define OFF_LOCS    0
#define OFF_SCORES  700000
#define OFF_ROIS    1050000
#define OFF_RIDX    1052400
#define OFF_RVALID  1053000
#define OFF_ANCH    1053600

// ---------------- device scratch (no allocation allowed; self-cleaning across replays) ----------------
__device__ __align__(16) float g_pad[2 * NCH * QPAD];
__device__ __align__(16) float g_h[2 * NCH * NPIX];
__device__ __align__(16) float g_scores[2 * 70 * NPIX];
__device__ __align__(16) float g_locs[2 * 140 * NPIX];
__device__ float4 g_anchors2[NANCH];     // a-major: [a][p]
__device__ u64    g_keys[2 * NANCH];
__device__ float4 g_boxes[2 * NANCH];
__device__ int    g_cnt[2];              // zeroed by merge_gather (post-use)
__device__ u64    g_top[2 * TOPCAP];
__device__ float4 g_nmsbox[2 * PRE_NMS];
__device__ u64    g_mask[(size_t)2 * PRE_NMS * NW];
__device__ u64    g_validb[2 * NW];      // zeroed by local_sort (pre-use)
__device__ u32    g_hist1[2 * 65536];    // zeroed by scan_kernel pass 0 (post-read)
__device__ u32    g_hist2[2 * 65536];    // zeroed by scan_kernel pass 1 (post-read)
__device__ u32    g_prefix[2];
__device__ u32    g_rank[2];
__device__ u32    g_thresh[2];

// ---------------- init: pad input + anchors, fused ----------------
__global__ void init_kernel(const float* __restrict__ feat, float* __restrict__ out)
{
    int idx = blockIdx.x * blockDim.x + threadIdx.x;
    if (idx < 2 * NCH * QPAD) {
        int plane = idx / QPAD;
        int q = idx - plane * QPAD;
        int i = q / HPAD, j = q - i * HPAD;
        float v = 0.f;
        if (i >= 1 && i <= 50 && j >= 1 && j <= 50)
            v = feat[(size_t)plane * NPIX + (i - 1) * 50 + (j - 1)];
        g_pad[idx] = v;
    }
    if (idx < NANCH) {
        int p = idx / NA, a = idx - p * NA;
        int ri = a / 5, si = a - ri * 5;
        const double RAT[7] = {0.5, 0.66, 0.75, 1.0, 1.33, 1.5, 2.0};
        const double SCL[5] = {2.0, 4.0, 8.0, 16.0, 32.0};
        double hh = 16.0 * SCL[si] * sqrt(RAT[ri]);
        double ww = 16.0 * SCL[si] * sqrt(1.0 / RAT[ri]);
        float a0 = (float)(8.0 - hh / 2.0);
        float a1 = (float)(8.0 - ww / 2.0);
        float a2 = (float)(8.0 + hh / 2.0);
        float a3 = (float)(8.0 + ww / 2.0);
        int iy = p / 50, jx = p - iy * 50;
        float sy = (float)(iy * 16), sx = (float)(jx * 16);
        float y1 = fminf(fmaxf(a0 + sy, 0.f), 799.f);
        float x1 = fminf(fmaxf(a1 + sx, 0.f), 799.f);
        float y2 = fminf(fmaxf(a2 + sy, 0.f), 799.f);
        float x2 = fminf(fmaxf(a3 + sx, 0.f), 799.f);
        g_anchors2[a * NPIX + p] = make_float4(y1, x1, y2, x2);
        size_t o = OFF_ANCH + (size_t)idx * 4;
        out[o + 0] = y1; out[o + 1] = x1; out[o + 2] = y2; out[o + 3] = x2;
    }
}

// ---------------- conv3x3 + bias + relu as implicit GEMM, double-buffered ----------------
#define PTILE 80
__global__ void __launch_bounds__(256, 2)
conv3x3_kernel(const float* __restrict__ W, const float* __restrict__ bias)
{
    const int bx = blockIdx.x;
    const int by = blockIdx.y;
    const int bz = blockIdx.z;
    const int tid = threadIdx.x;
    const int n0 = bx * PTILE;
    const int m0 = by * 128;
    __shared__ __align__(16) float As[2][8][128];
    __shared__ __align__(16) float Bs[2][8][PTILE];
    const int tm = tid >> 4;
    const int tn = tid & 15;
    float acc[8][5];
#pragma unroll
    for (int u = 0; u < 8; u++)
#pragma unroll
        for (int v = 0; v < 5; v++) acc[u][v] = 0.f;

    const int a_co = tid >> 1;
    const int a_kq = (tid & 1) * 4;
    const int b_kk = tid >> 5;
    const int b_px = tid & 31;
    const float* padB = g_pad + (size_t)bz * NCH * QPAD;
    const float* wrow = W + (size_t)(m0 + a_co) * KTOT + a_kq;

    int poff[3];
    bool pok[3];
#pragma unroll
    for (int e = 0; e < 3; e++) {
        int px = b_px + e * 32;
        int p = n0 + px;
        pok[e] = (px < PTILE) && (p < NPIX);
        int i = pok[e] ? (p / 50) : 0;
        int j = pok[e] ? (p - 50 * i) : 0;
        poff[e] = i * HPAD + j;
    }

    float4 av;
    float bv[3];
    {
        av = *(const float4*)&wrow[0];
        int k = b_kk;
        int ci = k / 9;
        int r = k - ci * 9;
        int dy = r / 3, dx = r - dy * 3;
        const float* pp = padB + (size_t)ci * QPAD + dy * HPAD + dx;
#pragma unroll
        for (int e = 0; e < 3; e++) bv[e] = pok[e] ? pp[poff[e]] : 0.f;
    }
    As[0][a_kq + 0][a_co] = av.x;
    As[0][a_kq + 1][a_co] = av.y;
    As[0][a_kq + 2][a_co] = av.z;
    As[0][a_kq + 3][a_co] = av.w;
#pragma unroll
    for (int e = 0; e < 3; e++) {
        int px = b_px + e * 32;
        if (px < PTILE) Bs[0][b_kk][px] = bv[e];
    }
    __syncthreads();

    for (int k0 = 0; k0 < KTOT; k0 += 8) {
        int buf = (k0 >> 3) & 1;
        bool more = (k0 + 8 < KTOT);
        if (more) {
            av = *(const float4*)&wrow[k0 + 8];
            int k = k0 + 8 + b_kk;
            int ci = k / 9;
            int r = k - ci * 9;
            int dy = r / 3, dx = r - dy * 3;
            const float* pp = padB + (size_t)ci * QPAD + dy * HPAD + dx;
#pragma unroll
            for (int e = 0; e < 3; e++) bv[e] = pok[e] ? pp[poff[e]] : 0.f;
        }
#pragma unroll
        for (int kk = 0; kk < 8; kk++) {
            float4 aa0 = *(const float4*)&As[buf][kk][tm * 8];
            float4 aa1 = *(const float4*)&As[buf][kk][tm * 8 + 4];
            float aarr[8] = {aa0.x, aa0.y, aa0.z, aa0.w, aa1.x, aa1.y, aa1.z, aa1.w};
            float barr[5];
#pragma unroll
            for (int v = 0; v < 5; v++) barr[v] = Bs[buf][kk][tn * 5 + v];
#pragma unroll
            for (int u = 0; u < 8; u++)
#pragma unroll
                for (int v = 0; v < 5; v++)
                    acc[u][v] = fmaf(aarr[u], barr[v], acc[u][v]);
        }
        if (more) {
            int nb = buf ^ 1;
            As[nb][a_kq + 0][a_co] = av.x;
            As[nb][a_kq + 1][a_co] = av.y;
            As[nb][a_kq + 2][a_co] = av.z;
            As[nb][a_kq + 3][a_co] = av.w;
#pragma unroll
            for (int e = 0; e < 3; e++) {
                int px = b_px + e * 32;
                if (px < PTILE) Bs[nb][b_kk][px] = bv[e];
            }
            __syncthreads();
        }
    }
#pragma unroll
    for (int u = 0; u < 8; u++) {
        int co = m0 + tm * 8 + u;
        float bb = bias[co];
        float* outrow = g_h + ((size_t)bz * NCH + co) * NPIX;
#pragma unroll
        for (int v = 0; v < 5; v++) {
            int p = n0 + tn * 5 + v;
            if (p < NPIX) outrow[p] = fmaxf(acc[u][v] + bb, 0.f);
        }
    }
}

// ---------------- 1x1 conv GEMM (scores + locs merged), double-buffered ----------------
__global__ void __launch_bounds__(256)
gemm1x1_kernel(const float* __restrict__ scorew, const float* __restrict__ scoreb,
               const float* __restrict__ locw, const float* __restrict__ locb)
{
    const int bx = blockIdx.x;
    const int byr = blockIdx.y;
    const int bz = blockIdx.z;
    const int tid = threadIdx.x;
    const float* W;
    const float* bias;
    float* outbase;
    int M, m0;
    if (byr < 2) { W = scorew; bias = scoreb; outbase = g_scores; M = 70; m0 = byr * 64; }
    else         { W = locw;   bias = locb;   outbase = g_locs;   M = 140; m0 = (byr - 2) * 64; }
    const int n0 = bx * 64;
    __shared__ __align__(16) float As[2][16][64];
    __shared__ __align__(16) float Bs[2][16][64];
    const int tm = tid >> 4, tn = tid & 15;
    float acc[4][4];
#pragma unroll
    for (int u = 0; u < 4; u++)
#pragma unroll
        for (int v = 0; v < 4; v++) acc[u][v] = 0.f;

    const int a_co = tid >> 2;
    const int a_kq = (tid & 3) * 4;
    const int b_kk = tid >> 4;
    const int b_p0 = (tid & 15) * 4;
    const float* Hb = g_h + (size_t)bz * NCH * NPIX;
    const int co = m0 + a_co;
    const int p0 = n0 + b_p0;
    const float4 z4 = make_float4(0.f, 0.f, 0.f, 0.f);

    float4 av = (co < M) ? *(const float4*)&W[(size_t)co * NCH + a_kq] : z4;
    float4 bv = (p0 < NPIX) ? *(const float4*)&Hb[(size_t)b_kk * NPIX + p0] : z4;
    As[0][a_kq + 0][a_co] = av.x;
    As[0][a_kq + 1][a_co] = av.y;
    As[0][a_kq + 2][a_co] = av.z;
    As[0][a_kq + 3][a_co] = av.w;
    *(float4*)&Bs[0][b_kk][b_p0] = bv;
    __syncthreads();

    for (int k0 = 0; k0 < NCH; k0 += 16) {
        int buf = (k0 >> 4) & 1;
        bool more = (k0 + 16 < NCH);
        if (more) {
            av = (co < M) ? *(const float4*)&W[(size_t)co * NCH + k0 + 16 + a_kq] : z4;
            bv = (p0 < NPIX) ? *(const float4*)&Hb[(size_t)(k0 + 16 + b_kk) * NPIX + p0] : z4;
        }
#pragma unroll
        for (int kk = 0; kk < 16; kk++) {
            float4 aa = *(const float4*)&As[buf][kk][tm * 4];
            float4 bb = *(const float4*)&Bs[buf][kk][tn * 4];
            float aarr[4] = {aa.x, aa.y, aa.z, aa.w};
            float barr[4] = {bb.x, bb.y, bb.z, bb.w};
#pragma unroll
            for (int u = 0; u < 4; u++)
#pragma unroll
                for (int v = 0; v < 4; v++)
                    acc[u][v] = fmaf(aarr[u], barr[v], acc[u][v]);
        }
        if (more) {
            int nb = buf ^ 1;
            As[nb][a_kq + 0][a_co] = av.x;
            As[nb][a_kq + 1][a_co] = av.y;
            As[nb][a_kq + 2][a_co] = av.z;
            As[nb][a_kq + 3][a_co] = av.w;
            *(float4*)&Bs[nb][b_kk][b_p0] = bv;
            __syncthreads();
        }
    }
#pragma unroll
    for (int u = 0; u < 4; u++) {
        int cu = m0 + tm * 4 + u;
        if (cu >= M) continue;
        float bb = bias[cu];
        float* orow = outbase + ((size_t)bz * M + cu) * NPIX;
#pragma unroll
        for (int v = 0; v < 4; v++) {
            int p = n0 + tn * 4 + v;
            if (p < NPIX) orow[p] = acc[u][v] + bb;
        }
    }
}

// ---------------- decode boxes + fused histogram pass 0 ----------------
__global__ void decode_kernel(float* __restrict__ out)
{
    __shared__ int sneg[2];
    if (threadIdx.x < 2) sneg[threadIdx.x] = 0;
    __syncthreads();

    int t = blockIdx.x * blockDim.x + threadIdx.x;
    int lane = threadIdx.x & 31;
    bool in = (t < 2 * NANCH);
    int b = 0;
    u32 bin = 0;
    if (in) {
        b = t / NANCH;
        int r = t - b * NANCH;
        int a = r / NPIX;
        int p = r - a * NPIX;
        int pa = p * NA + a;

        const float* sc = g_scores + (size_t)b * 70 * NPIX;
        float x0 = sc[(a * 2 + 0) * NPIX + p];
        float x1 = sc[(a * 2 + 1) * NPIX + p];
        size_t so = OFF_SCORES + (size_t)b * 175000 + (size_t)pa * 2;
        out[so + 0] = x0;
        out[so + 1] = x1;
        float mx = fmaxf(x0, x1);
        float e0 = expf(x0 - mx), e1 = expf(x1 - mx);
        float fg = e1 / (e0 + e1);

        const float* lc = g_locs + (size_t)b * 140 * NPIX;
        float dy  = lc[(a * 4 + 0) * NPIX + p];
        float dx_ = lc[(a * 4 + 1) * NPIX + p];
        float dh  = lc[(a * 4 + 2) * NPIX + p];
        float dw  = lc[(a * 4 + 3) * NPIX + p];
        size_t lo = OFF_LOCS + (size_t)b * 350000 + (size_t)pa * 4;
        out[lo + 0] = dy; out[lo + 1] = dx_; out[lo + 2] = dh; out[lo + 3] = dw;

        float4 an = g_anchors2[a * NPIX + p];
        float ah = an.z - an.x, aw = an.w - an.y;
        float acy = an.x + 0.5f * ah, acx = an.y + 0.5f * aw;
        float cy = dy * ah + acy, cx = dx_ * aw + acx;
        float hh = expf(dh) * ah, ww = expf(dw) * aw;
        float y1 = cy - 0.5f * hh, x1b = cx - 0.5f * ww;
        float y2 = cy + 0.5f * hh, x2b = cx + 0.5f * ww;
        y1 = fminf(fmaxf(y1, 0.f), 800.f);
        x1b = fminf(fmaxf(x1b, 0.f), 800.f);
        y2 = fminf(fmaxf(y2, 0.f), 800.f);
        x2b = fminf(fmaxf(x2b, 0.f), 800.f);
        float hs = y2 - y1, ws = x2b - x1b;
        bool valid = (hs >= 16.f) && (ws >= 16.f);
        float s = valid ? fg : -__int_as_float(0x7f800000);

        u32 sb = __float_as_uint(s);
        u32 mm = (sb & 0x80000000u) ? ~sb : (sb | 0x80000000u);
        u64 key = ((u64)(~mm) << 32) | (u32)pa;   // ascending key = best first
        g_keys[(size_t)b * NANCH + pa] = key;
        g_boxes[(size_t)b * NANCH + pa] = make_float4(y1, x1b, y2, x2b);
        bin = (u32)(key >> 48);
    }
    unsigned act = __ballot_sync(0xffffffffu, in);
    if (in) {
        u32 tag = (u32)b << 16 | bin;
        unsigned grp = __match_any_sync(act, tag);
        int leader = __ffs(grp) - 1;
        if (lane == leader) {
            if (bin == 0xFF80u) atomicAdd(&sneg[b], (int)__popc(grp));
            else                atomicAdd(&g_hist1[b * 65536 + bin], (u32)__popc(grp));
        }
    }
    __syncthreads();
    if (threadIdx.x < 2 && sneg[threadIdx.x] > 0)
        atomicAdd(&g_hist1[threadIdx.x * 65536 + 0xFF80], (u32)sneg[threadIdx.x]);
}

// ---------------- histogram pass 1 (16-bit digits, warp-aggregated atomics) ----------------
__global__ void hist_kernel()
{
    int idx = blockIdx.x * blockDim.x + threadIdx.x;
    int lane = threadIdx.x & 31;
    bool ok = (idx < 2 * NANCH);
    int b = 0;
    u32 bin = 0;
    if (ok) {
        b = idx / NANCH;
        u64 k = g_keys[idx];
        if ((u32)(k >> 48) == g_prefix[b]) bin = (u32)((k >> 32) & 0xffffu);
        else ok = false;
    }
    unsigned act = __ballot_sync(0xffffffffu, ok);
    if (ok) {
        u32 tag = (u32)b << 16 | bin;
        unsigned grp = __match_any_sync(act, tag);
        int leader = __ffs(grp) - 1;
        if (lane == leader)
            atomicAdd(&g_hist2[b * 65536 + bin], (u32)__popc(grp));
    }
}

// ---------------- scan 65536 bins, locate rank; self-clean own bins AFTER rank-find ----------------
// each thread owns bins [tid*64, tid*64+64); rank-find reads only own bins (still intact),
// zeroing follows in program order per thread -> no cross-thread hazard, no reg-array needed
__global__ void __launch_bounds__(1024)
scan_kernel(int pass)
{
    int b = blockIdx.x;
    int tid = threadIdx.x;  // 1024
    u32* base = (pass == 0 ? g_hist1 : g_hist2) + b * 65536;
    __shared__ u32 ssum[1024];
    u32 local = 0;
    const uint4* b4 = (const uint4*)(base + tid * 64);
#pragma unroll
    for (int j = 0; j < 16; j++) {
        uint4 v4 = b4[j];
        local += v4.x + v4.y + v4.z + v4.w;
    }
    ssum[tid] = local;
    __syncthreads();
    for (int off = 1; off < 1024; off <<= 1) {
        u32 v = (tid >= off) ? ssum[tid - off] : 0;
        __syncthreads();
        ssum[tid] += v;
        __syncthreads();
    }
    u32 incl = ssum[tid];
    u32 excl = incl - local;
    u32 rank = (pass == 0) ? (PRE_NMS - 1) : g_rank[b];
    if (excl <= rank && rank < incl) {
        u32 run = excl;
        for (int j = 0; j < 64; j++) {
            u32 c = base[tid * 64 + j];      // own bins, not yet zeroed
            if (run + c > rank) {
                u32 digit = (u32)(tid * 64 + j);
                g_rank[b] = rank - run;
                if (pass == 0) g_prefix[b] = digit;
                else g_thresh[b] = (g_prefix[b] << 16) | digit;
                break;
            }
            run += c;
        }
    }
    // self-clean own bins (after this thread's rank-find)
    uint4* w4 = (uint4*)(base + tid * 64);
    uint4 z4 = make_uint4(0, 0, 0, 0);
#pragma unroll
    for (int j = 0; j < 16; j++) w4[j] = z4;
}

// ---------------- compact keys with score32 <= thresh (warp-aggregated, per-batch) ----------------
__global__ void compact_kernel()
{
    int idx = blockIdx.x * blockDim.x + threadIdx.x;
    int lane = threadIdx.x & 31;
    bool ok = false;
    int b = 0;
    u64 k = 0;
    if (idx < 2 * NANCH) {
        b = idx / NANCH;
        k = g_keys[idx];
        ok = ((u32)(k >> 32) <= g_thresh[b]);
    }
#pragma unroll
    for (int bb = 0; bb < 2; bb++) {
        unsigned m = __ballot_sync(0xffffffffu, ok && b == bb);
        if (m) {
            int leader = __ffs(m) - 1;
            int base = 0;
            if (lane == leader) base = atomicAdd(&g_cnt[bb], __popc(m));
            base = __shfl_sync(0xffffffffu, base, leader);
            if (ok && b == bb) {
                int pos = base + __popc(m & ((1u << lane) - 1));
                if (pos < TOPCAP) g_top[(size_t)bb * TOPCAP + pos] = k;
            }
        }
    }
}

// ---------------- bitonic sort, local phase: k=2..1024 within 1024-aligned runs ----------------
// also zeroes g_validb (pre-use; merge_gather sets bits next)
__global__ void __launch_bounds__(1024)
local_sort_kernel()
{
    __shared__ u64 s[1024];
    int m = blockIdx.x;       // 0..7
    int b = blockIdx.y;
    int lt = threadIdx.x;
    if (m == 0 && lt < NW) g_validb[b * NW + lt] = 0ull;
    int base = m * 1024;
    int cnt = g_cnt[b];
    if (cnt > TOPCAP) cnt = TOPCAP;
    int gi = base + lt;
    s[lt] = (gi < cnt) ? g_top[(size_t)b * TOPCAP + gi] : ~0ull;
    __syncthreads();
    for (int k = 2; k <= 1024; k <<= 1) {
        for (int j = k >> 1; j > 0; j >>= 1) {
            int ixj = lt ^ j;
            if (ixj > lt) {
                bool up = (((base + lt) & k) == 0);
                u64 x = s[lt], y = s[ixj];
                if ((x > y) == up) { s[lt] = y; s[ixj] = x; }
            }
            __syncthreads();
        }
    }
    g_top[(size_t)b * TOPCAP + gi] = s[lt];
}

// ---------------- bitonic merge k=2048..8192 + fused gather; resets g_cnt (post-use) ----------------
__global__ void __launch_bounds__(1024)
merge_gather_kernel()
{
    extern __shared__ u64 s[];
    int b = blockIdx.x;
    int tid = threadIdx.x;
    for (int i = tid; i < TOPCAP; i += 1024)
        s[i] = g_top[(size_t)b * TOPCAP + i];
    if (tid == 0) g_cnt[b] = 0;     // self-clean for next replay (local_sort was last reader)
    __syncthreads();
    for (int k = 2048; k <= TOPCAP; k <<= 1) {
        for (int j = k >> 1; j > 0; j >>= 1) {
            for (int t = tid; t < TOPCAP; t += 1024) {
                int ixj = t ^ j;
                if (ixj > t) {
                    bool up = ((t & k) == 0);
                    u64 x = s[t], y = s[ixj];
                    if ((x > y) == up) { s[t] = y; s[ixj] = x; }
                }
            }
            __syncthreads();
        }
    }
    for (int i = tid; i < PRE_NMS; i += 1024) {
        u64 k = s[i];
        u32 ai = (u32)(k & 0xffffffffull);
        g_nmsbox[(size_t)b * PRE_NMS + i] = g_boxes[(size_t)b * NANCH + ai];
        bool valid = ((u32)(k >> 32)) != 0xFF800000u;
        if (valid) atomicOr(&g_validb[b * NW + (i >> 6)], 1ull << (i & 63));
    }
}

// ---------------- NMS IoU bitmask (triangular grid) ----------------
__global__ void nms_mask_kernel()
{
    int t = blockIdx.x;
    int b = blockIdx.y;
    int rb = (int)((2.0 * NW + 1.0 - sqrt((2.0 * NW + 1.0) * (2.0 * NW + 1.0) - 8.0 * t)) * 0.5);
    if (rb < 0) rb = 0;
    if (rb > NW - 1) rb = NW - 1;
    while (rb > 0 && (rb * NW - rb * (rb - 1) / 2) > t) rb--;
    while (rb < NW - 1 && ((rb + 1) * NW - (rb + 1) * rb / 2) <= t) rb++;
    int cb = rb + (t - (rb * NW - rb * (rb - 1) / 2));

    int tid = threadIdx.x;
    __shared__ float4 cbox[64];
    int j = cb * 64 + tid;
    cbox[tid] = (j < PRE_NMS) ? g_nmsbox[(size_t)b * PRE_NMS + j]
                              : make_float4(0.f, 0.f, 0.f, 0.f);
    __syncthreads();
    int i = rb * 64 + tid;
    if (i >= PRE_NMS) return;
    float4 rr = g_nmsbox[(size_t)b * PRE_NMS + i];
    float areai = (rr.z - rr.x) * (rr.w - rr.y);
    u64 bits = 0ull;
    if (cb > rb) {
#pragma unroll 4
        for (int c = 0; c < 64; c++) {
            float4 cc = cbox[c];
            float ty = fmaxf(rr.x, cc.x), tx = fmaxf(rr.y, cc.y);
            float by = fminf(rr.z, cc.z), bx2 = fminf(rr.w, cc.w);
            float wy = fmaxf(by - ty, 0.f), wx = fmaxf(bx2 - tx, 0.f);
            float inter = wy * wx;
            float areaj = (cc.z - cc.x) * (cc.w - cc.y);
            float iou = inter / (areai + areaj - inter + 1e-9f);
            if (iou > 0.7f) bits |= 1ull << c;
        }
    } else {
        for (int c = tid + 1; c < 64; c++) {
            float4 cc = cbox[c];
            float ty = fmaxf(rr.x, cc.x), tx = fmaxf(rr.y, cc.y);
            float by = fminf(rr.z, cc.z), bx2 = fminf(rr.w, cc.w);
            float wy = fmaxf(by - ty, 0.f), wx = fmaxf(bx2 - tx, 0.f);
            float inter = wy * wx;
            float areaj = (cc.z - cc.x) * (cc.w - cc.y);
            float iou = inter / (areai + areaj - inter + 1e-9f);
            if (iou > 0.7f) bits |= 1ull << c;
        }
    }
    g_mask[((size_t)b * PRE_NMS + i) * NW + cb] = bits;
}

// ---------------- NMS reduction v5 + fused finalize ----------------
__global__ void __launch_bounds__(512)
nms_reduce_finalize_kernel(float* __restrict__ out)
{
    int b = blockIdx.x;
    int tid = threadIdx.x;
    __shared__ u64 diag[2][64];
    __shared__ u64 remv[NW];
    __shared__ u64 svalid[NW];
    __shared__ u64 kw[NW];
    __shared__ int klist[64];
    __shared__ int snk;
    for (int v = tid; v < NW; v += 512) {
        remv[v] = 0ull;
        svalid[v] = g_validb[b * NW + v];
    }
    if (tid < 64)
        diag[0][tid] = (tid < PRE_NMS) ? g_mask[((size_t)b * PRE_NMS + tid) * NW + 0] : 0ull;
    __syncthreads();

    for (int w = 0; w < NW; w++) {
        int buf = w & 1;
        u64 rv = 0ull;
        if (w + 1 < NW && tid < 64) {
            int i = (w + 1) * 64 + tid;
            if (i < PRE_NMS) rv = g_mask[((size_t)b * PRE_NMS + i) * NW + (w + 1)];
        }
        if (tid == 0) {
            u64 cur = svalid[w] & ~remv[w];
            u64 kp = 0ull;
            int nk = 0;
            while (cur) {
                int bit = __ffsll((long long)cur) - 1;
                kp |= (1ull << bit);
                klist[nk++] = w * 64 + bit;
                cur &= ~diag[buf][bit];
                cur &= ~(1ull << bit);
            }
            snk = nk;
            kw[w] = kp;
        }
        __syncthreads();
        if (w + 1 < NW && tid < 64) diag[buf ^ 1][tid] = rv;
        int nk = snk;
        if (nk > 0) {
            int nv = NW - 1 - w;
            int total = nk * nv;
            for (int e0 = tid; e0 < total; e0 += 4096) {
                u64 mv[8];
                int vv[8];
#pragma unroll
                for (int s2 = 0; s2 < 8; s2++) {
                    int e = e0 + s2 * 512;
                    mv[s2] = 0ull;
                    vv[s2] = w + 1;
                    if (e < total) {
                        int q = e / nv;
                        int v = w + 1 + (e - q * nv);
                        vv[s2] = v;
                        mv[s2] = g_mask[((size_t)b * PRE_NMS + klist[q]) * NW + v];
                    }
                }
#pragma unroll
                for (int s2 = 0; s2 < 8; s2++)
                    if (mv[s2]) atomicOr(&remv[vv[s2]], mv[s2]);
            }
        }
        __syncthreads();
    }

    // ---- fused finalize ----
    __shared__ u32 kscan[NW];
    __shared__ u32 ktot;
    __shared__ int sel[POST_NMS];
    if (tid == 0) {
        u32 r = 0;
        for (int w = 0; w < NW; w++) { kscan[w] = r; r += (u32)__popcll(kw[w]); }
        ktot = r;
    }
    __syncthreads();
    u32 ktot_l = ktot;
    for (int w = tid; w < NW; w += 512) {
        u64 bits = kw[w];
        u32 base = kscan[w];
        u64 t = bits;
        while (t) {
            int bit = __ffsll((long long)t) - 1;
            t &= t - 1;
            if (base < POST_NMS) sel[base] = w * 64 + bit;
            base++;
        }
        u64 lim = (w == NW - 1) ? ((1ull << 48) - 1ull) : ~0ull;  // 6000 = 93*64+48
        u64 nt = (~bits) & lim;
        while (nt) {
            int bit = __ffsll((long long)nt) - 1;
            nt &= nt - 1;
            int i = w * 64 + bit;
            u64 below = (bit == 0) ? 0ull : ((1ull << bit) - 1ull);
            u32 kept_before = kscan[w] + (u32)__popcll(bits & below);
            u32 slot = ktot_l + (u32)i - kept_before;
            if (slot < POST_NMS) sel[slot] = i;
        }
    }
    __syncthreads();
    for (int s2 = tid; s2 < POST_NMS; s2 += 512) {
        int i = sel[s2];
        int v = (int)((kw[i >> 6] >> (i & 63)) & 1ull);
        float4 bx = v ? g_nmsbox[(size_t)b * PRE_NMS + i] : make_float4(0.f, 0.f, 0.f, 0.f);
        size_t ro = OFF_ROIS + (size_t)b * POST_NMS * 4 + (size_t)s2 * 4;
        out[ro + 0] = bx.x; out[ro + 1] = bx.y; out[ro + 2] = bx.z; out[ro + 3] = bx.w;
        out[OFF_RIDX + (size_t)b * POST_NMS + s2] = (float)b;
        out[OFF_RVALID + (size_t)b * POST_NMS + s2] = (float)v;
    }
}

// ---------------- launch ----------------
extern "C" void kernel_launch(void* const* d_in, const int* in_sizes, int n_in,
                              void* d_out, int out_size)
{
    const float* feat   = (const float*)d_in[0];
    const float* convw  = (const float*)d_in[1];
    const float* convb  = (const float*)d_in[2];
    const float* scorew = (const float*)d_in[3];
    const float* scoreb = (const float*)d_in[4];
    const float* locw   = (const float*)d_in[5];
    const float* locb   = (const float*)d_in[6];
    float* out = (float*)d_out;

    cudaFuncSetAttribute(merge_gather_kernel, cudaFuncAttributeMaxDynamicSharedMemorySize, 65536);

    init_kernel<<<(2 * NCH * QPAD + 255) / 256, 256>>>(feat, out);           // 0
    conv3x3_kernel<<<dim3(32, 4, 2), 256>>>(convw, convb);                   // 1
    gemm1x1_kernel<<<dim3(40, 5, 2), 256>>>(scorew, scoreb, locw, locb);     // 2
    decode_kernel<<<(2 * NANCH + 255) / 256, 256>>>(out);                    // 3
    scan_kernel<<<2, 1024>>>(0);                                             // 4
    hist_kernel<<<(2 * NANCH + 255) / 256, 256>>>();                         // 5
    scan_kernel<<<2, 1024>>>(1);                                             // 6
    compact_kernel<<<(2 * NANCH + 255) / 256, 256>>>();                      // 7
    local_sort_kernel<<<dim3(8, 2), 1024>>>();                               // 8
    merge_gather_kernel<<<2, 1024, 65536>>>();                               // 9
    nms_mask_kernel<<<dim3(NTRI, 2), 64>>>();                                // 10
    nms_reduce_finalize_kernel<<<2, 512>>>(out);                             // 11
}

// round 16
// speedup vs baseline: 1.1169x; 1.0124x over previous
#include <cuda_runtime.h>
#include <cuda_bf16.h>
#include <math.h>

typedef unsigned int u32;
typedef unsigned long long u64;

// ---------------- problem constants ----------------
#define NPIX    2500
#define HPAD    52
#define QPAD    2704          // 52*52
#define NCH     512
#define KTOT    4608          // 512*9
#define NA      35
#define NANCH   87500         // 2500*35
#define PRE_NMS 6000
#define POST_NMS 300
#define NW      94            // ceil(6000/64)
#define NTRI    (NW * (NW + 1) / 2)
#define TOPCAP  8192

// output layout (float32, concatenated tuple)
#define OFF_LOCS    0
#define OFF_SCORES  700000
#define OFF_ROIS    1050000
#define OFF_RIDX    1052400
#define OFF_RVALID  1053000
#define OFF_ANCH    1053600

// ---------------- device scratch (no allocation allowed) ----------------
__device__ __align__(16) float g_pad[2 * NCH * QPAD];
__device__ __align__(16) float g_h[2 * NCH * NPIX];
__device__ __align__(16) float g_scores[2 * 70 * NPIX];
__device__ __align__(16) float g_locs[2 * 140 * NPIX];
__device__ float4 g_anchors2[NANCH];     // a-major: [a][p]
__device__ u32    g_keyhi[2 * NANCH];    // top-32 of sort key; pa encoded in index
__device__ float4 g_boxes[2 * NANCH];
__device__ int    g_cnt[2];
__device__ u64    g_top[2 * TOPCAP];
__device__ float4 g_nmsbox[2 * PRE_NMS];
__device__ u64    g_mask[(size_t)2 * PRE_NMS * NW];
__device__ u64    g_validb[2 * NW];
__device__ u32    g_hist1[2 * 65536];
__device__ u32    g_hist2[2 * 65536];
__device__ u32    g_prefix[2];
__device__ u32    g_rank[2];
__device__ u32    g_thresh[2];

// ---------------- init: pad input + zero scratch + anchors, fused ----------------
__global__ void init_kernel(const float* __restrict__ feat, float* __restrict__ out)
{
    int idx = blockIdx.x * blockDim.x + threadIdx.x;
    if (idx < 2 * NCH * QPAD) {
        int plane = idx / QPAD;
        int q = idx - plane * QPAD;
        int i = q / HPAD, j = q - i * HPAD;
        float v = 0.f;
        if (i >= 1 && i <= 50 && j >= 1 && j <= 50)
            v = feat[(size_t)plane * NPIX + (i - 1) * 50 + (j - 1)];
        g_pad[idx] = v;
    }
    if (idx < 2) g_cnt[idx] = 0;
    if (idx < 2 * NW) g_validb[idx] = 0ull;
    if (idx < 2 * 65536) { g_hist1[idx] = 0; g_hist2[idx] = 0; }
    if (idx < NANCH) {
        int p = idx / NA, a = idx - p * NA;
        int ri = a / 5, si = a - ri * 5;
        const double RAT[7] = {0.5, 0.66, 0.75, 1.0, 1.33, 1.5, 2.0};
        const double SCL[5] = {2.0, 4.0, 8.0, 16.0, 32.0};
        double hh = 16.0 * SCL[si] * sqrt(RAT[ri]);
        double ww = 16.0 * SCL[si] * sqrt(1.0 / RAT[ri]);
        float a0 = (float)(8.0 - hh / 2.0);
        float a1 = (float)(8.0 - ww / 2.0);
        float a2 = (float)(8.0 + hh / 2.0);
        float a3 = (float)(8.0 + ww / 2.0);
        int iy = p / 50, jx = p - iy * 50;
        float sy = (float)(iy * 16), sx = (float)(jx * 16);
        float y1 = fminf(fmaxf(a0 + sy, 0.f), 799.f);
        float x1 = fminf(fmaxf(a1 + sx, 0.f), 799.f);
        float y2 = fminf(fmaxf(a2 + sy, 0.f), 799.f);
        float x2 = fminf(fmaxf(a3 + sx, 0.f), 799.f);
        g_anchors2[a * NPIX + p] = make_float4(y1, x1, y2, x2);
        size_t o = OFF_ANCH + (size_t)idx * 4;
        out[o + 0] = y1; out[o + 1] = x1; out[o + 2] = y2; out[o + 3] = x2;
    }
}

// ---------------- conv3x3 + bias + relu as implicit GEMM, double-buffered ----------------
// proven best shape: 128co x 80pix, 256 threads, 8x5 micro, occ-2 (~750us, 98% of fp32 issue floor)
#define PTILE 80
__global__ void __launch_bounds__(256, 2)
conv3x3_kernel(const float* __restrict__ W, const float* __restrict__ bias)
{
    const int bx = blockIdx.x;
    const int by = blockIdx.y;
    const int bz = blockIdx.z;
    const int tid = threadIdx.x;
    const int n0 = bx * PTILE;
    const int m0 = by * 128;
    __shared__ __align__(16) float As[2][8][128];
    __shared__ __align__(16) float Bs[2][8][PTILE];
    const int tm = tid >> 4;
    const int tn = tid & 15;
    float acc[8][5];
#pragma unroll
    for (int u = 0; u < 8; u++)
#pragma unroll
        for (int v = 0; v < 5; v++) acc[u][v] = 0.f;

    const int a_co = tid >> 1;
    const int a_kq = (tid & 1) * 4;
    const int b_kk = tid >> 5;
    const int b_px = tid & 31;
    const float* padB = g_pad + (size_t)bz * NCH * QPAD;
    const float* wrow = W + (size_t)(m0 + a_co) * KTOT + a_kq;

    int poff[3];
    bool pok[3];
#pragma unroll
    for (int e = 0; e < 3; e++) {
        int px = b_px + e * 32;
        int p = n0 + px;
        pok[e] = (px < PTILE) && (p < NPIX);
        int i = pok[e] ? (p / 50) : 0;
        int j = pok[e] ? (p - 50 * i) : 0;
        poff[e] = i * HPAD + j;
    }

    float4 av;
    float bv[3];
    {
        av = *(const float4*)&wrow[0];
        int k = b_kk;
        int ci = k / 9;
        int r = k - ci * 9;
        int dy = r / 3, dx = r - dy * 3;
        const float* pp = padB + (size_t)ci * QPAD + dy * HPAD + dx;
#pragma unroll
        for (int e = 0; e < 3; e++) bv[e] = pok[e] ? pp[poff[e]] : 0.f;
    }
    As[0][a_kq + 0][a_co] = av.x;
    As[0][a_kq + 1][a_co] = av.y;
    As[0][a_kq + 2][a_co] = av.z;
    As[0][a_kq + 3][a_co] = av.w;
#pragma unroll
    for (int e = 0; e < 3; e++) {
        int px = b_px + e * 32;
        if (px < PTILE) Bs[0][b_kk][px] = bv[e];
    }
    __syncthreads();

    for (int k0 = 0; k0 < KTOT; k0 += 8) {
        int buf = (k0 >> 3) & 1;
        bool more = (k0 + 8 < KTOT);
        if (more) {
            av = *(const float4*)&wrow[k0 + 8];
            int k = k0 + 8 + b_kk;
            int ci = k / 9;
            int r = k - ci * 9;
            int dy = r / 3, dx = r - dy * 3;
            const float* pp = padB + (size_t)ci * QPAD + dy * HPAD + dx;
#pragma unroll
            for (int e = 0; e < 3; e++) bv[e] = pok[e] ? pp[poff[e]] : 0.f;
        }
#pragma unroll
        for (int kk = 0; kk < 8; kk++) {
            float4 aa0 = *(const float4*)&As[buf][kk][tm * 8];
            float4 aa1 = *(const float4*)&As[buf][kk][tm * 8 + 4];
            float aarr[8] = {aa0.x, aa0.y, aa0.z, aa0.w, aa1.x, aa1.y, aa1.z, aa1.w};
            float barr[5];
#pragma unroll
            for (int v = 0; v < 5; v++) barr[v] = Bs[buf][kk][tn * 5 + v];
#pragma unroll
            for (int u = 0; u < 8; u++)
#pragma unroll
                for (int v = 0; v < 5; v++)
                    acc[u][v] = fmaf(aarr[u], barr[v], acc[u][v]);
        }
        if (more) {
            int nb = buf ^ 1;
            As[nb][a_kq + 0][a_co] = av.x;
            As[nb][a_kq + 1][a_co] = av.y;
            As[nb][a_kq + 2][a_co] = av.z;
            As[nb][a_kq + 3][a_co] = av.w;
#pragma unroll
            for (int e = 0; e < 3; e++) {
                int px = b_px + e * 32;
                if (px < PTILE) Bs[nb][b_kk][px] = bv[e];
            }
            __syncthreads();
        }
    }
#pragma unroll
    for (int u = 0; u < 8; u++) {
        int co = m0 + tm * 8 + u;
        float bb = bias[co];
        float* outrow = g_h + ((size_t)bz * NCH + co) * NPIX;
#pragma unroll
        for (int v = 0; v < 5; v++) {
            int p = n0 + tn * 5 + v;
            if (p < NPIX) outrow[p] = fmaxf(acc[u][v] + bb, 0.f);
        }
    }
}

// ---------------- 1x1 conv GEMM (scores + locs merged), double-buffered ----------------
__global__ void __launch_bounds__(256)
gemm1x1_kernel(const float* __restrict__ scorew, const float* __restrict__ scoreb,
               const float* __restrict__ locw, const float* __restrict__ locb)
{
    const int bx = blockIdx.x;
    const int byr = blockIdx.y;
    const int bz = blockIdx.z;
    const int tid = threadIdx.x;
    const float* W;
    const float* bias;
    float* outbase;
    int M, m0;
    if (byr < 2) { W = scorew; bias = scoreb; outbase = g_scores; M = 70; m0 = byr * 64; }
    else         { W = locw;   bias = locb;   outbase = g_locs;   M = 140; m0 = (byr - 2) * 64; }
    const int n0 = bx * 64;
    __shared__ __align__(16) float As[2][16][64];
    __shared__ __align__(16) float Bs[2][16][64];
    const int tm = tid >> 4, tn = tid & 15;
    float acc[4][4];
#pragma unroll
    for (int u = 0; u < 4; u++)
#pragma unroll
        for (int v = 0; v < 4; v++) acc[u][v] = 0.f;

    const int a_co = tid >> 2;
    const int a_kq = (tid & 3) * 4;
    const int b_kk = tid >> 4;
    const int b_p0 = (tid & 15) * 4;
    const float* Hb = g_h + (size_t)bz * NCH * NPIX;
    const int co = m0 + a_co;
    const int p0 = n0 + b_p0;
    const float4 z4 = make_float4(0.f, 0.f, 0.f, 0.f);

    float4 av = (co < M) ? *(const float4*)&W[(size_t)co * NCH + a_kq] : z4;
    float4 bv = (p0 < NPIX) ? *(const float4*)&Hb[(size_t)b_kk * NPIX + p0] : z4;
    As[0][a_kq + 0][a_co] = av.x;
    As[0][a_kq + 1][a_co] = av.y;
    As[0][a_kq + 2][a_co] = av.z;
    As[0][a_kq + 3][a_co] = av.w;
    *(float4*)&Bs[0][b_kk][b_p0] = bv;
    __syncthreads();

    for (int k0 = 0; k0 < NCH; k0 += 16) {
        int buf = (k0 >> 4) & 1;
        bool more = (k0 + 16 < NCH);
        if (more) {
            av = (co < M) ? *(const float4*)&W[(size_t)co * NCH + k0 + 16 + a_kq] : z4;
            bv = (p0 < NPIX) ? *(const float4*)&Hb[(size_t)(k0 + 16 + b_kk) * NPIX + p0] : z4;
        }
#pragma unroll
        for (int kk = 0; kk < 16; kk++) {
            float4 aa = *(const float4*)&As[buf][kk][tm * 4];
            float4 bb = *(const float4*)&Bs[buf][kk][tn * 4];
            float aarr[4] = {aa.x, aa.y, aa.z, aa.w};
            float barr[4] = {bb.x, bb.y, bb.z, bb.w};
#pragma unroll
            for (int u = 0; u < 4; u++)
#pragma unroll
                for (int v = 0; v < 4; v++)
                    acc[u][v] = fmaf(aarr[u], barr[v], acc[u][v]);
        }
        if (more) {
            int nb = buf ^ 1;
            As[nb][a_kq + 0][a_co] = av.x;
            As[nb][a_kq + 1][a_co] = av.y;
            As[nb][a_kq + 2][a_co] = av.z;
            As[nb][a_kq + 3][a_co] = av.w;
            *(float4*)&Bs[nb][b_kk][b_p0] = bv;
            __syncthreads();
        }
    }
#pragma unroll
    for (int u = 0; u < 4; u++) {
        int cu = m0 + tm * 4 + u;
        if (cu >= M) continue;
        float bb = bias[cu];
        float* orow = outbase + ((size_t)bz * M + cu) * NPIX;
#pragma unroll
        for (int v = 0; v < 4; v++) {
            int p = n0 + tn * 4 + v;
            if (p < NPIX) orow[p] = acc[u][v] + bb;
        }
    }
}

// ---------------- decode boxes + fused histogram pass 0 (stores 32-bit key-hi only) ----------------
__global__ void decode_kernel(float* __restrict__ out)
{
    __shared__ int sneg[2];
    if (threadIdx.x < 2) sneg[threadIdx.x] = 0;
    __syncthreads();

    int t = blockIdx.x * blockDim.x + threadIdx.x;
    int lane = threadIdx.x & 31;
    bool in = (t < 2 * NANCH);
    int b = 0;
    u32 bin = 0;
    if (in) {
        b = t / NANCH;
        int r = t - b * NANCH;
        int a = r / NPIX;
        int p = r - a * NPIX;
        int pa = p * NA + a;

        const float* sc = g_scores + (size_t)b * 70 * NPIX;
        float x0 = sc[(a * 2 + 0) * NPIX + p];
        float x1 = sc[(a * 2 + 1) * NPIX + p];
        size_t so = OFF_SCORES + (size_t)b * 175000 + (size_t)pa * 2;
        out[so + 0] = x0;
        out[so + 1] = x1;
        float mx = fmaxf(x0, x1);
        float e0 = expf(x0 - mx), e1 = expf(x1 - mx);
        float fg = e1 / (e0 + e1);

        const float* lc = g_locs + (size_t)b * 140 * NPIX;
        float dy  = lc[(a * 4 + 0) * NPIX + p];
        float dx_ = lc[(a * 4 + 1) * NPIX + p];
        float dh  = lc[(a * 4 + 2) * NPIX + p];
        float dw  = lc[(a * 4 + 3) * NPIX + p];
        size_t lo = OFF_LOCS + (size_t)b * 350000 + (size_t)pa * 4;
        out[lo + 0] = dy; out[lo + 1] = dx_; out[lo + 2] = dh; out[lo + 3] = dw;

        float4 an = g_anchors2[a * NPIX + p];
        float ah = an.z - an.x, aw = an.w - an.y;
        float acy = an.x + 0.5f * ah, acx = an.y + 0.5f * aw;
        float cy = dy * ah + acy, cx = dx_ * aw + acx;
        float hh = expf(dh) * ah, ww = expf(dw) * aw;
        float y1 = cy - 0.5f * hh, x1b = cx - 0.5f * ww;
        float y2 = cy + 0.5f * hh, x2b = cx + 0.5f * ww;
        y1 = fminf(fmaxf(y1, 0.f), 800.f);
        x1b = fminf(fmaxf(x1b, 0.f), 800.f);
        y2 = fminf(fmaxf(y2, 0.f), 800.f);
        x2b = fminf(fmaxf(x2b, 0.f), 800.f);
        float hs = y2 - y1, ws = x2b - x1b;
        bool valid = (hs >= 16.f) && (ws >= 16.f);
        float s = valid ? fg : -__int_as_float(0x7f800000);

        u32 sb = __float_as_uint(s);
        u32 mm = (sb & 0x80000000u) ? ~sb : (sb | 0x80000000u);
        u32 hi = ~mm;                                   // ascending: best first
        g_keyhi[(size_t)b * NANCH + pa] = hi;
        g_boxes[(size_t)b * NANCH + pa] = make_float4(y1, x1b, y2, x2b);
        bin = hi >> 16;
    }
    unsigned act = __ballot_sync(0xffffffffu, in);
    if (in) {
        u32 tag = (u32)b << 16 | bin;
        unsigned grp = __match_any_sync(act, tag);
        int leader = __ffs(grp) - 1;
        if (lane == leader) {
            if (bin == 0xFF80u) atomicAdd(&sneg[b], (int)__popc(grp));
            else                atomicAdd(&g_hist1[b * 65536 + bin], (u32)__popc(grp));
        }
    }
    __syncthreads();
    if (threadIdx.x < 2 && sneg[threadIdx.x] > 0)
        atomicAdd(&g_hist1[threadIdx.x * 65536 + 0xFF80], (u32)sneg[threadIdx.x]);
}

// ---------------- histogram pass 1 (16-bit digits, warp-aggregated atomics) ----------------
__global__ void hist_kernel()
{
    int idx = blockIdx.x * blockDim.x + threadIdx.x;
    int lane = threadIdx.x & 31;
    bool ok = (idx < 2 * NANCH);
    int b = 0;
    u32 bin = 0;
    if (ok) {
        b = idx / NANCH;
        u32 hi = g_keyhi[idx];
        if ((hi >> 16) == g_prefix[b]) bin = hi & 0xffffu;
        else ok = false;
    }
    unsigned act = __ballot_sync(0xffffffffu, ok);
    if (ok) {
        u32 tag = (u32)b << 16 | bin;
        unsigned grp = __match_any_sync(act, tag);
        int leader = __ffs(grp) - 1;
        if (lane == leader)
            atomicAdd(&g_hist2[b * 65536 + bin], (u32)__popc(grp));
    }
}

// ---------------- scan 65536 bins, locate rank (uint4 loads) ----------------
__global__ void __launch_bounds__(1024)
scan_kernel(int pass)
{
    int b = blockIdx.x;
    int tid = threadIdx.x;  // 1024
    const u32* base = (pass == 0 ? g_hist1 : g_hist2) + b * 65536;
    __shared__ u32 ssum[1024];
    u32 local = 0;
    const uint4* b4 = (const uint4*)(base + tid * 64);
#pragma unroll
    for (int j = 0; j < 16; j++) {
        uint4 v4 = b4[j];
        local += v4.x + v4.y + v4.z + v4.w;
    }
    ssum[tid] = local;
    __syncthreads();
    for (int off = 1; off < 1024; off <<= 1) {
        u32 v = (tid >= off) ? ssum[tid - off] : 0;
        __syncthreads();
        ssum[tid] += v;
        __syncthreads();
    }
    u32 incl = ssum[tid];
    u32 excl = incl - local;
    u32 rank = (pass == 0) ? (PRE_NMS - 1) : g_rank[b];
    if (excl <= rank && rank < incl) {
        u32 run = excl;
        for (int j = 0; j < 64; j++) {
            u32 c = base[tid * 64 + j];
            if (run + c > rank) {
                u32 digit = (u32)(tid * 64 + j);
                g_rank[b] = rank - run;
                if (pass == 0) g_prefix[b] = digit;
                else g_thresh[b] = (g_prefix[b] << 16) | digit;
                break;
            }
            run += c;
        }
    }
}

// ---------------- compact: key reconstructed from (hi, index) — bit-identical ----------------
__global__ void compact_kernel()
{
    int idx = blockIdx.x * blockDim.x + threadIdx.x;
    int lane = threadIdx.x & 31;
    bool ok = false;
    int b = 0;
    u64 k = 0;
    if (idx < 2 * NANCH) {
        b = idx / NANCH;
        u32 hi = g_keyhi[idx];
        ok = (hi <= g_thresh[b]);
        k = ((u64)hi << 32) | (u32)(idx - b * NANCH);
    }
#pragma unroll
    for (int bb = 0; bb < 2; bb++) {
        unsigned m = __ballot_sync(0xffffffffu, ok && b == bb);
        if (m) {
            int leader = __ffs(m) - 1;
            int base = 0;
            if (lane == leader) base = atomicAdd(&g_cnt[bb], __popc(m));
            base = __shfl_sync(0xffffffffu, base, leader);
            if (ok && b == bb) {
                int pos = base + __popc(m & ((1u << lane) - 1));
                if (pos < TOPCAP) g_top[(size_t)bb * TOPCAP + pos] = k;
            }
        }
    }
}

// ---------------- bitonic sort, local phase: k=2..1024 within 1024-aligned runs ----------------
__global__ void __launch_bounds__(1024)
local_sort_kernel()
{
    __shared__ u64 s[1024];
    int m = blockIdx.x;       // 0..7
    int b = blockIdx.y;
    int lt = threadIdx.x;
    int base = m * 1024;
    int cnt = g_cnt[b];
    if (cnt > TOPCAP) cnt = TOPCAP;
    int gi = base + lt;
    s[lt] = (gi < cnt) ? g_top[(size_t)b * TOPCAP + gi] : ~0ull;
    __syncthreads();
    for (int k = 2; k <= 1024; k <<= 1) {
        for (int j = k >> 1; j > 0; j >>= 1) {
            int ixj = lt ^ j;
            if (ixj > lt) {
                bool up = (((base + lt) & k) == 0);
                u64 x = s[lt], y = s[ixj];
                if ((x > y) == up) { s[lt] = y; s[ixj] = x; }
            }
            __syncthreads();
        }
    }
    g_top[(size_t)b * TOPCAP + gi] = s[lt];
}

// ---------------- bitonic merge k=2048..8192 + fused gather epilogue ----------------
__global__ void __launch_bounds__(1024)
merge_gather_kernel()
{
    extern __shared__ u64 s[];
    int b = blockIdx.x;
    int tid = threadIdx.x;
    for (int i = tid; i < TOPCAP; i += 1024)
        s[i] = g_top[(size_t)b * TOPCAP + i];
    __syncthreads();
    for (int k = 2048; k <= TOPCAP; k <<= 1) {
        for (int j = k >> 1; j > 0; j >>= 1) {
            for (int t = tid; t < TOPCAP; t += 1024) {
                int ixj = t ^ j;
                if (ixj > t) {
                    bool up = ((t & k) == 0);
                    u64 x = s[t], y = s[ixj];
                    if ((x > y) == up) { s[t] = y; s[ixj] = x; }
                }
            }
            __syncthreads();
        }
    }
    for (int i = tid; i < PRE_NMS; i += 1024) {
        u64 k = s[i];
        u32 ai = (u32)(k & 0xffffffffull);
        g_nmsbox[(size_t)b * PRE_NMS + i] = g_boxes[(size_t)b * NANCH + ai];
        bool valid = ((u32)(k >> 32)) != 0xFF800000u;
        if (valid) atomicOr(&g_validb[b * NW + (i >> 6)], 1ull << (i & 63));
    }
}

// ---------------- NMS IoU bitmask (triangular grid) ----------------
__global__ void nms_mask_kernel()
{
    int t = blockIdx.x;
    int b = blockIdx.y;
    int rb = (int)((2.0 * NW + 1.0 - sqrt((2.0 * NW + 1.0) * (2.0 * NW + 1.0) - 8.0 * t)) * 0.5);
    if (rb < 0) rb = 0;
    if (rb > NW - 1) rb = NW - 1;
    while (rb > 0 && (rb * NW - rb * (rb - 1) / 2) > t) rb--;
    while (rb < NW - 1 && ((rb + 1) * NW - (rb + 1) * rb / 2) <= t) rb++;
    int cb = rb + (t - (rb * NW - rb * (rb - 1) / 2));

    int tid = threadIdx.x;
    __shared__ float4 cbox[64];
    int j = cb * 64 + tid;
    cbox[tid] = (j < PRE_NMS) ? g_nmsbox[(size_t)b * PRE_NMS + j]
                              : make_float4(0.f, 0.f, 0.f, 0.f);
    __syncthreads();
    int i = rb * 64 + tid;
    if (i >= PRE_NMS) return;
    float4 rr = g_nmsbox[(size_t)b * PRE_NMS + i];
    float areai = (rr.z - rr.x) * (rr.w - rr.y);
    u64 bits = 0ull;
    if (cb > rb) {
#pragma unroll 4
        for (int c = 0; c < 64; c++) {
            float4 cc = cbox[c];
            float ty = fmaxf(rr.x, cc.x), tx = fmaxf(rr.y, cc.y);
            float by = fminf(rr.z, cc.z), bx2 = fminf(rr.w, cc.w);
            float wy = fmaxf(by - ty, 0.f), wx = fmaxf(bx2 - tx, 0.f);
            float inter = wy * wx;
            float areaj = (cc.z - cc.x) * (cc.w - cc.y);
            float iou = inter / (areai + areaj - inter + 1e-9f);
            if (iou > 0.7f) bits |= 1ull << c;
        }
    } else {
        for (int c = tid + 1; c < 64; c++) {
            float4 cc = cbox[c];
            float ty = fmaxf(rr.x, cc.x), tx = fmaxf(rr.y, cc.y);
            float by = fminf(rr.z, cc.z), bx2 = fminf(rr.w, cc.w);
            float wy = fmaxf(by - ty, 0.f), wx = fmaxf(bx2 - tx, 0.f);
            float inter = wy * wx;
            float areaj = (cc.z - cc.x) * (cc.w - cc.y);
            float iou = inter / (areai + areaj - inter + 1e-9f);
            if (iou > 0.7f) bits |= 1ull << c;
        }
    }
    g_mask[((size_t)b * PRE_NMS + i) * NW + cb] = bits;
}

// ---------------- NMS reduction v5 + fused finalize ----------------
__global__ void __launch_bounds__(512)
nms_reduce_finalize_kernel(float* __restrict__ out)
{
    int b = blockIdx.x;
    int tid = threadIdx.x;
    __shared__ u64 diag[2][64];
    __shared__ u64 remv[NW];
    __shared__ u64 svalid[NW];
    __shared__ u64 kw[NW];
    __shared__ int klist[64];
    __shared__ int snk;
    for (int v = tid; v < NW; v += 512) {
        remv[v] = 0ull;
        svalid[v] = g_validb[b * NW + v];
    }
    if (tid < 64)
        diag[0][tid] = (tid < PRE_NMS) ? g_mask[((size_t)b * PRE_NMS + tid) * NW + 0] : 0ull;
    __syncthreads();

    for (int w = 0; w < NW; w++) {
        int buf = w & 1;
        u64 rv = 0ull;
        if (w + 1 < NW && tid < 64) {
            int i = (w + 1) * 64 + tid;
            if (i < PRE_NMS) rv = g_mask[((size_t)b * PRE_NMS + i) * NW + (w + 1)];
        }
        if (tid == 0) {
            u64 cur = svalid[w] & ~remv[w];
            u64 kp = 0ull;
            int nk = 0;
            while (cur) {
                int bit = __ffsll((long long)cur) - 1;
                kp |= (1ull << bit);
                klist[nk++] = w * 64 + bit;
                cur &= ~diag[buf][bit];
                cur &= ~(1ull << bit);
            }
            snk = nk;
            kw[w] = kp;
        }
        __syncthreads();
        if (w + 1 < NW && tid < 64) diag[buf ^ 1][tid] = rv;
        int nk = snk;
        if (nk > 0) {
            int nv = NW - 1 - w;
            int total = nk * nv;
            for (int e0 = tid; e0 < total; e0 += 4096) {
                u64 mv[8];
                int vv[8];
#pragma unroll
                for (int s2 = 0; s2 < 8; s2++) {
                    int e = e0 + s2 * 512;
                    mv[s2] = 0ull;
                    vv[s2] = w + 1;
                    if (e < total) {
                        int q = e / nv;
                        int v = w + 1 + (e - q * nv);
                        vv[s2] = v;
                        mv[s2] = g_mask[((size_t)b * PRE_NMS + klist[q]) * NW + v];
                    }
                }
#pragma unroll
                for (int s2 = 0; s2 < 8; s2++)
                    if (mv[s2]) atomicOr(&remv[vv[s2]], mv[s2]);
            }
        }
        __syncthreads();
    }

    // ---- fused finalize ----
    __shared__ u32 kscan[NW];
    __shared__ u32 ktot;
    __shared__ int sel[POST_NMS];
    if (tid == 0) {
        u32 r = 0;
        for (int w = 0; w < NW; w++) { kscan[w] = r; r += (u32)__popcll(kw[w]); }
        ktot = r;
    }
    __syncthreads();
    u32 ktot_l = ktot;
    for (int w = tid; w < NW; w += 512) {
        u64 bits = kw[w];
        u32 base = kscan[w];
        u64 t = bits;
        while (t) {
            int bit = __ffsll((long long)t) - 1;
            t &= t - 1;
            if (base < POST_NMS) sel[base] = w * 64 + bit;
            base++;
        }
        u64 lim = (w == NW - 1) ? ((1ull << 48) - 1ull) : ~0ull;  // 6000 = 93*64+48
        u64 nt = (~bits) & lim;
        while (nt) {
            int bit = __ffsll((long long)nt) - 1;
            nt &= nt - 1;
            int i = w * 64 + bit;
            u64 below = (bit == 0) ? 0ull : ((1ull << bit) - 1ull);
            u32 kept_before = kscan[w] + (u32)__popcll(bits & below);
            u32 slot = ktot_l + (u32)i - kept_before;
            if (slot < POST_NMS) sel[slot] = i;
        }
    }
    __syncthreads();
    for (int s2 = tid; s2 < POST_NMS; s2 += 512) {
        int i = sel[s2];
        int v = (int)((kw[i >> 6] >> (i & 63)) & 1ull);
        float4 bx = v ? g_nmsbox[(size_t)b * PRE_NMS + i] : make_float4(0.f, 0.f, 0.f, 0.f);
        size_t ro = OFF_ROIS + (size_t)b * POST_NMS * 4 + (size_t)s2 * 4;
        out[ro + 0] = bx.x; out[ro + 1] = bx.y; out[ro + 2] = bx.z; out[ro + 3] = bx.w;
        out[OFF_RIDX + (size_t)b * POST_NMS + s2] = (float)b;
        out[OFF_RVALID + (size_t)b * POST_NMS + s2] = (float)v;
    }
}

// ---------------- launch ----------------
extern "C" void kernel_launch(void* const* d_in, const int* in_sizes, int n_in,
                              void* d_out, int out_size)
{
    const float* feat   = (const float*)d_in[0];
    const float* convw  = (const float*)d_in[1];
    const float* convb  = (const float*)d_in[2];
    const float* scorew = (const float*)d_in[3];
    const float* scoreb = (const float*)d_in[4];
    const float* locw   = (const float*)d_in[5];
    const float* locb   = (const float*)d_in[6];
    float* out = (float*)d_out;

    cudaFuncSetAttribute(merge_gather_kernel, cudaFuncAttributeMaxDynamicSharedMemorySize, 65536);

    init_kernel<<<(2 * NCH * QPAD + 255) / 256, 256>>>(feat, out);           // 0
    conv3x3_kernel<<<dim3(32, 4, 2), 256>>>(convw, convb);                   // 1
    gemm1x1_kernel<<<dim3(40, 5, 2), 256>>>(scorew, scoreb, locw, locb);     // 2
    decode_kernel<<<(2 * NANCH + 255) / 256, 256>>>(out);                    // 3
    scan_kernel<<<2, 1024>>>(0);                                             // 4
    hist_kernel<<<(2 * NANCH + 255) / 256, 256>>>();                         // 5
    scan_kernel<<<2, 1024>>>(1);                                             // 6
    compact_kernel<<<(2 * NANCH + 255) / 256, 256>>>();                      // 7
    local_sort_kernel<<<dim3(8, 2), 1024>>>();                               // 8
    merge_gather_kernel<<<2, 1024, 65536>>>();                               // 9
    nms_mask_kernel<<<dim3(NTRI, 2), 64>>>();                                // 10
    nms_reduce_finalize_kernel<<<2, 512>>>(out);                             // 11
}

// round 17
// speedup vs baseline: 1.1205x; 1.0032x over previous
#include <cuda_runtime.h>
#include <cuda_bf16.h>
#include <math.h>

typedef unsigned int u32;
typedef unsigned long long u64;

// ---------------- problem constants ----------------
#define NPIX    2500
#define HPAD    52
#define QPAD    2704          // 52*52
#define NCH     512
#define KTOT    4608          // 512*9
#define NA      35
#define NANCH   87500         // 2500*35
#define PRE_NMS 6000
#define POST_NMS 300
#define NW      94            // ceil(6000/64)
#define NTRI    (NW * (NW + 1) / 2)
#define TOPCAP  8192

// output layout (float32, concatenated tuple)
#define OFF_LOCS    0
#define OFF_SCORES  700000
#define OFF_ROIS    1050000
#define OFF_RIDX    1052400
#define OFF_RVALID  1053000
#define OFF_ANCH    1053600

// wait for upstream grid's writes (PDL)
#define GRID_DEP_SYNC() cudaGridDependencySynchronize()

// ---------------- device scratch (no allocation allowed) ----------------
__device__ __align__(16) float g_pad[2 * NCH * QPAD];
__device__ __align__(16) float g_h[2 * NCH * NPIX];
__device__ __align__(16) float g_scores[2 * 70 * NPIX];
__device__ __align__(16) float g_locs[2 * 140 * NPIX];
__device__ float4 g_anchors2[NANCH];     // a-major: [a][p]
__device__ u32    g_keyhi[2 * NANCH];    // top-32 of sort key; pa encoded in index
__device__ float4 g_boxes[2 * NANCH];
__device__ int    g_cnt[2];
__device__ u64    g_top[2 * TOPCAP];
__device__ float4 g_nmsbox[2 * PRE_NMS];
__device__ u64    g_mask[(size_t)2 * PRE_NMS * NW];
__device__ u64    g_validb[2 * NW];
__device__ u32    g_hist1[2 * 65536];
__device__ u32    g_hist2[2 * 65536];
__device__ u32    g_prefix[2];
__device__ u32    g_rank[2];
__device__ u32    g_thresh[2];

// ---------------- init: pad input + zero scratch + anchors, fused ----------------
__global__ void init_kernel(const float* __restrict__ feat, float* __restrict__ out)
{
    int idx = blockIdx.x * blockDim.x + threadIdx.x;
    if (idx < 2 * NCH * QPAD) {
        int plane = idx / QPAD;
        int q = idx - plane * QPAD;
        int i = q / HPAD, j = q - i * HPAD;
        float v = 0.f;
        if (i >= 1 && i <= 50 && j >= 1 && j <= 50)
            v = feat[(size_t)plane * NPIX + (i - 1) * 50 + (j - 1)];
        g_pad[idx] = v;
    }
    if (idx < 2) g_cnt[idx] = 0;
    if (idx < 2 * NW) g_validb[idx] = 0ull;
    if (idx < 2 * 65536) { g_hist1[idx] = 0; g_hist2[idx] = 0; }
    if (idx < NANCH) {
        int p = idx / NA, a = idx - p * NA;
        int ri = a / 5, si = a - ri * 5;
        const double RAT[7] = {0.5, 0.66, 0.75, 1.0, 1.33, 1.5, 2.0};
        const double SCL[5] = {2.0, 4.0, 8.0, 16.0, 32.0};
        double hh = 16.0 * SCL[si] * sqrt(RAT[ri]);
        double ww = 16.0 * SCL[si] * sqrt(1.0 / RAT[ri]);
        float a0 = (float)(8.0 - hh / 2.0);
        float a1 = (float)(8.0 - ww / 2.0);
        float a2 = (float)(8.0 + hh / 2.0);
        float a3 = (float)(8.0 + ww / 2.0);
        int iy = p / 50, jx = p - iy * 50;
        float sy = (float)(iy * 16), sx = (float)(jx * 16);
        float y1 = fminf(fmaxf(a0 + sy, 0.f), 799.f);
        float x1 = fminf(fmaxf(a1 + sx, 0.f), 799.f);
        float y2 = fminf(fmaxf(a2 + sy, 0.f), 799.f);
        float x2 = fminf(fmaxf(a3 + sx, 0.f), 799.f);
        g_anchors2[a * NPIX + p] = make_float4(y1, x1, y2, x2);
        size_t o = OFF_ANCH + (size_t)idx * 4;
        out[o + 0] = y1; out[o + 1] = x1; out[o + 2] = y2; out[o + 3] = x2;
    }
}

// ---------------- conv3x3 + bias + relu as implicit GEMM, double-buffered ----------------
#define PTILE 80
__global__ void __launch_bounds__(256, 2)
conv3x3_kernel(const float* __restrict__ W, const float* __restrict__ bias)
{
    const int bx = blockIdx.x;
    const int by = blockIdx.y;
    const int bz = blockIdx.z;
    const int tid = threadIdx.x;
    const int n0 = bx * PTILE;
    const int m0 = by * 128;
    __shared__ __align__(16) float As[2][8][128];
    __shared__ __align__(16) float Bs[2][8][PTILE];
    const int tm = tid >> 4;
    const int tn = tid & 15;
    float acc[8][5];
#pragma unroll
    for (int u = 0; u < 8; u++)
#pragma unroll
        for (int v = 0; v < 5; v++) acc[u][v] = 0.f;

    const int a_co = tid >> 1;
    const int a_kq = (tid & 1) * 4;
    const int b_kk = tid >> 5;
    const int b_px = tid & 31;
    const float* padB = g_pad + (size_t)bz * NCH * QPAD;
    const float* wrow = W + (size_t)(m0 + a_co) * KTOT + a_kq;

    int poff[3];
    bool pok[3];
#pragma unroll
    for (int e = 0; e < 3; e++) {
        int px = b_px + e * 32;
        int p = n0 + px;
        pok[e] = (px < PTILE) && (p < NPIX);
        int i = pok[e] ? (p / 50) : 0;
        int j = pok[e] ? (p - 50 * i) : 0;
        poff[e] = i * HPAD + j;
    }

    GRID_DEP_SYNC();   // wait for init's g_pad

    float4 av;
    float bv[3];
    {
        av = *(const float4*)&wrow[0];
        int k = b_kk;
        int ci = k / 9;
        int r = k - ci * 9;
        int dy = r / 3, dx = r - dy * 3;
        const float* pp = padB + (size_t)ci * QPAD + dy * HPAD + dx;
#pragma unroll
        for (int e = 0; e < 3; e++) bv[e] = pok[e] ? pp[poff[e]] : 0.f;
    }
    As[0][a_kq + 0][a_co] = av.x;
    As[0][a_kq + 1][a_co] = av.y;
    As[0][a_kq + 2][a_co] = av.z;
    As[0][a_kq + 3][a_co] = av.w;
#pragma unroll
    for (int e = 0; e < 3; e++) {
        int px = b_px + e * 32;
        if (px < PTILE) Bs[0][b_kk][px] = bv[e];
    }
    __syncthreads();

    for (int k0 = 0; k0 < KTOT; k0 += 8) {
        int buf = (k0 >> 3) & 1;
        bool more = (k0 + 8 < KTOT);
        if (more) {
            av = *(const float4*)&wrow[k0 + 8];
            int k = k0 + 8 + b_kk;
            int ci = k / 9;
            int r = k - ci * 9;
            int dy = r / 3, dx = r - dy * 3;
            const float* pp = padB + (size_t)ci * QPAD + dy * HPAD + dx;
#pragma unroll
            for (int e = 0; e < 3; e++) bv[e] = pok[e] ? pp[poff[e]] : 0.f;
        }
#pragma unroll
        for (int kk = 0; kk < 8; kk++) {
            float4 aa0 = *(const float4*)&As[buf][kk][tm * 8];
            float4 aa1 = *(const float4*)&As[buf][kk][tm * 8 + 4];
            float aarr[8] = {aa0.x, aa0.y, aa0.z, aa0.w, aa1.x, aa1.y, aa1.z, aa1.w};
            float barr[5];
#pragma unroll
            for (int v = 0; v < 5; v++) barr[v] = Bs[buf][kk][tn * 5 + v];
#pragma unroll
            for (int u = 0; u < 8; u++)
#pragma unroll
                for (int v = 0; v < 5; v++)
                    acc[u][v] = fmaf(aarr[u], barr[v], acc[u][v]);
        }
        if (more) {
            int nb = buf ^ 1;
            As[nb][a_kq + 0][a_co] = av.x;
            As[nb][a_kq + 1][a_co] = av.y;
            As[nb][a_kq + 2][a_co] = av.z;
            As[nb][a_kq + 3][a_co] = av.w;
#pragma unroll
            for (int e = 0; e < 3; e++) {
                int px = b_px + e * 32;
                if (px < PTILE) Bs[nb][b_kk][px] = bv[e];
            }
            __syncthreads();
        }
    }
#pragma unroll
    for (int u = 0; u < 8; u++) {
        int co = m0 + tm * 8 + u;
        float bb = bias[co];
        float* outrow = g_h + ((size_t)bz * NCH + co) * NPIX;
#pragma unroll
        for (int v = 0; v < 5; v++) {
            int p = n0 + tn * 5 + v;
            if (p < NPIX) outrow[p] = fmaxf(acc[u][v] + bb, 0.f);
        }
    }
}

// ---------------- 1x1 conv GEMM (scores + locs merged), double-buffered ----------------
__global__ void __launch_bounds__(256)
gemm1x1_kernel(const float* __restrict__ scorew, const float* __restrict__ scoreb,
               const float* __restrict__ locw, const float* __restrict__ locb)
{
    const int bx = blockIdx.x;
    const int byr = blockIdx.y;
    const int bz = blockIdx.z;
    const int tid = threadIdx.x;
    const float* W;
    const float* bias;
    float* outbase;
    int M, m0;
    if (byr < 2) { W = scorew; bias = scoreb; outbase = g_scores; M = 70; m0 = byr * 64; }
    else         { W = locw;   bias = locb;   outbase = g_locs;   M = 140; m0 = (byr - 2) * 64; }
    const int n0 = bx * 64;
    __shared__ __align__(16) float As[2][16][64];
    __shared__ __align__(16) float Bs[2][16][64];
    const int tm = tid >> 4, tn = tid & 15;
    float acc[4][4];
#pragma unroll
    for (int u = 0; u < 4; u++)
#pragma unroll
        for (int v = 0; v < 4; v++) acc[u][v] = 0.f;

    const int a_co = tid >> 2;
    const int a_kq = (tid & 3) * 4;
    const int b_kk = tid >> 4;
    const int b_p0 = (tid & 15) * 4;
    const float* Hb = g_h + (size_t)bz * NCH * NPIX;
    const int co = m0 + a_co;
    const int p0 = n0 + b_p0;
    const float4 z4 = make_float4(0.f, 0.f, 0.f, 0.f);

    GRID_DEP_SYNC();   // wait for conv's g_h

    float4 av = (co < M) ? *(const float4*)&W[(size_t)co * NCH + a_kq] : z4;
    float4 bv = (p0 < NPIX) ? *(const float4*)&Hb[(size_t)b_kk * NPIX + p0] : z4;
    As[0][a_kq + 0][a_co] = av.x;
    As[0][a_kq + 1][a_co] = av.y;
    As[0][a_kq + 2][a_co] = av.z;
    As[0][a_kq + 3][a_co] = av.w;
    *(float4*)&Bs[0][b_kk][b_p0] = bv;
    __syncthreads();

    for (int k0 = 0; k0 < NCH; k0 += 16) {
        int buf = (k0 >> 4) & 1;
        bool more = (k0 + 16 < NCH);
        if (more) {
            av = (co < M) ? *(const float4*)&W[(size_t)co * NCH + k0 + 16 + a_kq] : z4;
            bv = (p0 < NPIX) ? *(const float4*)&Hb[(size_t)(k0 + 16 + b_kk) * NPIX + p0] : z4;
        }
#pragma unroll
        for (int kk = 0; kk < 16; kk++) {
            float4 aa = *(const float4*)&As[buf][kk][tm * 4];
            float4 bb = *(const float4*)&Bs[buf][kk][tn * 4];
            float aarr[4] = {aa.x, aa.y, aa.z, aa.w};
            float barr[4] = {bb.x, bb.y, bb.z, bb.w};
#pragma unroll
            for (int u = 0; u < 4; u++)
#pragma unroll
                for (int v = 0; v < 4; v++)
                    acc[u][v] = fmaf(aarr[u], barr[v], acc[u][v]);
        }
        if (more) {
            int nb = buf ^ 1;
            As[nb][a_kq + 0][a_co] = av.x;
            As[nb][a_kq + 1][a_co] = av.y;
            As[nb][a_kq + 2][a_co] = av.z;
            As[nb][a_kq + 3][a_co] = av.w;
            *(float4*)&Bs[nb][b_kk][b_p0] = bv;
            __syncthreads();
        }
    }
#pragma unroll
    for (int u = 0; u < 4; u++) {
        int cu = m0 + tm * 4 + u;
        if (cu >= M) continue;
        float bb = bias[cu];
        float* orow = outbase + ((size_t)bz * M + cu) * NPIX;
#pragma unroll
        for (int v = 0; v < 4; v++) {
            int p = n0 + tn * 4 + v;
            if (p < NPIX) orow[p] = acc[u][v] + bb;
        }
    }
}

// ---------------- decode boxes + fused histogram pass 0 (stores 32-bit key-hi only) ----------------
__global__ void decode_kernel(float* __restrict__ out)
{
    __shared__ int sneg[2];
    if (threadIdx.x < 2) sneg[threadIdx.x] = 0;
    __syncthreads();

    GRID_DEP_SYNC();   // wait for gemm's g_scores / g_locs

    int t = blockIdx.x * blockDim.x + threadIdx.x;
    int lane = threadIdx.x & 31;
    bool in = (t < 2 * NANCH);
    int b = 0;
    u32 bin = 0;
    if (in) {
        b = t / NANCH;
        int r = t - b * NANCH;
        int a = r / NPIX;
        int p = r - a * NPIX;
        int pa = p * NA + a;

        const float* sc = g_scores + (size_t)b * 70 * NPIX;
        float x0 = sc[(a * 2 + 0) * NPIX + p];
        float x1 = sc[(a * 2 + 1) * NPIX + p];
        size_t so = OFF_SCORES + (size_t)b * 175000 + (size_t)pa * 2;
        out[so + 0] = x0;
        out[so + 1] = x1;
        float mx = fmaxf(x0, x1);
        float e0 = expf(x0 - mx), e1 = expf(x1 - mx);
        float fg = e1 / (e0 + e1);

        const float* lc = g_locs + (size_t)b * 140 * NPIX;
        float dy  = lc[(a * 4 + 0) * NPIX + p];
        float dx_ = lc[(a * 4 + 1) * NPIX + p];
        float dh  = lc[(a * 4 + 2) * NPIX + p];
        float dw  = lc[(a * 4 + 3) * NPIX + p];
        size_t lo = OFF_LOCS + (size_t)b * 350000 + (size_t)pa * 4;
        out[lo + 0] = dy; out[lo + 1] = dx_; out[lo + 2] = dh; out[lo + 3] = dw;

        float4 an = g_anchors2[a * NPIX + p];
        float ah = an.z - an.x, aw = an.w - an.y;
        float acy = an.x + 0.5f * ah, acx = an.y + 0.5f * aw;
        float cy = dy * ah + acy, cx = dx_ * aw + acx;
        float hh = expf(dh) * ah, ww = expf(dw) * aw;
        float y1 = cy - 0.5f * hh, x1b = cx - 0.5f * ww;
        float y2 = cy + 0.5f * hh, x2b = cx + 0.5f * ww;
        y1 = fminf(fmaxf(y1, 0.f), 800.f);
        x1b = fminf(fmaxf(x1b, 0.f), 800.f);
        y2 = fminf(fmaxf(y2, 0.f), 800.f);
        x2b = fminf(fmaxf(x2b, 0.f), 800.f);
        float hs = y2 - y1, ws = x2b - x1b;
        bool valid = (hs >= 16.f) && (ws >= 16.f);
        float s = valid ? fg : -__int_as_float(0x7f800000);

        u32 sb = __float_as_uint(s);
        u32 mm = (sb & 0x80000000u) ? ~sb : (sb | 0x80000000u);
        u32 hi = ~mm;                                   // ascending: best first
        g_keyhi[(size_t)b * NANCH + pa] = hi;
        g_boxes[(size_t)b * NANCH + pa] = make_float4(y1, x1b, y2, x2b);
        bin = hi >> 16;
    }
    unsigned act = __ballot_sync(0xffffffffu, in);
    if (in) {
        u32 tag = (u32)b << 16 | bin;
        unsigned grp = __match_any_sync(act, tag);
        int leader = __ffs(grp) - 1;
        if (lane == leader) {
            if (bin == 0xFF80u) atomicAdd(&sneg[b], (int)__popc(grp));
            else                atomicAdd(&g_hist1[b * 65536 + bin], (u32)__popc(grp));
        }
    }
    __syncthreads();
    if (threadIdx.x < 2 && sneg[threadIdx.x] > 0)
        atomicAdd(&g_hist1[threadIdx.x * 65536 + 0xFF80], (u32)sneg[threadIdx.x]);
}

// ---------------- histogram pass 1 (16-bit digits, warp-aggregated atomics) ----------------
__global__ void hist_kernel()
{
    GRID_DEP_SYNC();   // wait for scan pass 0's g_prefix
    int idx = blockIdx.x * blockDim.x + threadIdx.x;
    int lane = threadIdx.x & 31;
    bool ok = (idx < 2 * NANCH);
    int b = 0;
    u32 bin = 0;
    if (ok) {
        b = idx / NANCH;
        u32 hi = g_keyhi[idx];
        if ((hi >> 16) == g_prefix[b]) bin = hi & 0xffffu;
        else ok = false;
    }
    unsigned act = __ballot_sync(0xffffffffu, ok);
    if (ok) {
        u32 tag = (u32)b << 16 | bin;
        unsigned grp = __match_any_sync(act, tag);
        int leader = __ffs(grp) - 1;
        if (lane == leader)
            atomicAdd(&g_hist2[b * 65536 + bin], (u32)__popc(grp));
    }
}

// ---------------- scan 65536 bins, locate rank (uint4 loads) ----------------
__global__ void __launch_bounds__(1024)
scan_kernel(int pass)
{
    GRID_DEP_SYNC();   // wait for decode/hist histogram writes
    int b = blockIdx.x;
    int tid = threadIdx.x;  // 1024
    const u32* base = (pass == 0 ? g_hist1 : g_hist2) + b * 65536;
    __shared__ u32 ssum[1024];
    u32 local = 0;
    const uint4* b4 = (const uint4*)(base + tid * 64);
#pragma unroll
    for (int j = 0; j < 16; j++) {
        uint4 v4 = b4[j];
        local += v4.x + v4.y + v4.z + v4.w;
    }
    ssum[tid] = local;
    __syncthreads();
    for (int off = 1; off < 1024; off <<= 1) {
        u32 v = (tid >= off) ? ssum[tid - off] : 0;
        __syncthreads();
        ssum[tid] += v;
        __syncthreads();
    }
    u32 incl = ssum[tid];
    u32 excl = incl - local;
    u32 rank = (pass == 0) ? (PRE_NMS - 1) : g_rank[b];
    if (excl <= rank && rank < incl) {
        u32 run = excl;
        for (int j = 0; j < 64; j++) {
            u32 c = base[tid * 64 + j];
            if (run + c > rank) {
                u32 digit = (u32)(tid * 64 + j);
                g_rank[b] = rank - run;
                if (pass == 0) g_prefix[b] = digit;
                else g_thresh[b] = (g_prefix[b] << 16) | digit;
                break;
            }
            run += c;
        }
    }
}

// ---------------- compact: key reconstructed from (hi, index) — bit-identical ----------------
__global__ void compact_kernel()
{
    GRID_DEP_SYNC();   // wait for scan pass 1's g_thresh
    int idx = blockIdx.x * blockDim.x + threadIdx.x;
    int lane = threadIdx.x & 31;
    bool ok = false;
    int b = 0;
    u64 k = 0;
    if (idx < 2 * NANCH) {
        b = idx / NANCH;
        u32 hi = g_keyhi[idx];
        ok = (hi <= g_thresh[b]);
        k = ((u64)hi << 32) | (u32)(idx - b * NANCH);
    }
#pragma unroll
    for (int bb = 0; bb < 2; bb++) {
        unsigned m = __ballot_sync(0xffffffffu, ok && b == bb);
        if (m) {
            int leader = __ffs(m) - 1;
            int base = 0;
            if (lane == leader) base = atomicAdd(&g_cnt[bb], __popc(m));
            base = __shfl_sync(0xffffffffu, base, leader);
            if (ok && b == bb) {
                int pos = base + __popc(m & ((1u << lane) - 1));
                if (pos < TOPCAP) g_top[(size_t)bb * TOPCAP + pos] = k;
            }
        }
    }
}

// ---------------- bitonic sort, local phase: k=2..1024 within 1024-aligned runs ----------------
__global__ void __launch_bounds__(1024)
local_sort_kernel()
{
    __shared__ u64 s[1024];
    int m = blockIdx.x;       // 0..7
    int b = blockIdx.y;
    int lt = threadIdx.x;
    GRID_DEP_SYNC();   // wait for compact's g_top / g_cnt
    int base = m * 1024;
    int cnt = g_cnt[b];
    if (cnt > TOPCAP) cnt = TOPCAP;
    int gi = base + lt;
    s[lt] = (gi < cnt) ? g_top[(size_t)b * TOPCAP + gi] : ~0ull;
    __syncthreads();
    for (int k = 2; k <= 1024; k <<= 1) {
        for (int j = k >> 1; j > 0; j >>= 1) {
            int ixj = lt ^ j;
            if (ixj > lt) {
                bool up = (((base + lt) & k) == 0);
                u64 x = s[lt], y = s[ixj];
                if ((x > y) == up) { s[lt] = y; s[ixj] = x; }
            }
            __syncthreads();
        }
    }
    g_top[(size_t)b * TOPCAP + gi] = s[lt];
}

// ---------------- bitonic merge k=2048..8192 + fused gather epilogue ----------------
__global__ void __launch_bounds__(1024)
merge_gather_kernel()
{
    extern __shared__ u64 s[];
    int b = blockIdx.x;
    int tid = threadIdx.x;
    GRID_DEP_SYNC();   // wait for local_sort's g_top
    for (int i = tid; i < TOPCAP; i += 1024)
        s[i] = g_top[(size_t)b * TOPCAP + i];
    __syncthreads();
    for (int k = 2048; k <= TOPCAP; k <<= 1) {
        for (int j = k >> 1; j > 0; j >>= 1) {
            for (int t = tid; t < TOPCAP; t += 1024) {
                int ixj = t ^ j;
                if (ixj > t) {
                    bool up = ((t & k) == 0);
                    u64 x = s[t], y = s[ixj];
                    if ((x > y) == up) { s[t] = y; s[ixj] = x; }
                }
            }
            __syncthreads();
        }
    }
    for (int i = tid; i < PRE_NMS; i += 1024) {
        u64 k = s[i];
        u32 ai = (u32)(k & 0xffffffffull);
        g_nmsbox[(size_t)b * PRE_NMS + i] = g_boxes[(size_t)b * NANCH + ai];
        bool valid = ((u32)(k >> 32)) != 0xFF800000u;
        if (valid) atomicOr(&g_validb[b * NW + (i >> 6)], 1ull << (i & 63));
    }
}

// ---------------- NMS IoU bitmask (triangular grid) ----------------
__global__ void nms_mask_kernel()
{
    int t = blockIdx.x;
    int b = blockIdx.y;
    int rb = (int)((2.0 * NW + 1.0 - sqrt((2.0 * NW + 1.0) * (2.0 * NW + 1.0) - 8.0 * t)) * 0.5);
    if (rb < 0) rb = 0;
    if (rb > NW - 1) rb = NW - 1;
    while (rb > 0 && (rb * NW - rb * (rb - 1) / 2) > t) rb--;
    while (rb < NW - 1 && ((rb + 1) * NW - (rb + 1) * rb / 2) <= t) rb++;
    int cb = rb + (t - (rb * NW - rb * (rb - 1) / 2));

    int tid = threadIdx.x;
    __shared__ float4 cbox[64];
    GRID_DEP_SYNC();   // wait for merge_gather's g_nmsbox
    int j = cb * 64 + tid;
    cbox[tid] = (j < PRE_NMS) ? g_nmsbox[(size_t)b * PRE_NMS + j]
                              : make_float4(0.f, 0.f, 0.f, 0.f);
    __syncthreads();
    int i = rb * 64 + tid;
    if (i >= PRE_NMS) return;
    float4 rr = g_nmsbox[(size_t)b * PRE_NMS + i];
    float areai = (rr.z - rr.x) * (rr.w - rr.y);
    u64 bits = 0ull;
    if (cb > rb) {
#pragma unroll 4
        for (int c = 0; c < 64; c++) {
            float4 cc = cbox[c];
            float ty = fmaxf(rr.x, cc.x), tx = fmaxf(rr.y, cc.y);
            float by = fminf(rr.z, cc.z), bx2 = fminf(rr.w, cc.w);
            float wy = fmaxf(by - ty, 0.f), wx = fmaxf(bx2 - tx, 0.f);
            float inter = wy * wx;
            float areaj = (cc.z - cc.x) * (cc.w - cc.y);
            float iou = inter / (areai + areaj - inter + 1e-9f);
            if (iou > 0.7f) bits |= 1ull << c;
        }
    } else {
        for (int c = tid + 1; c < 64; c++) {
            float4 cc = cbox[c];
            float ty = fmaxf(rr.x, cc.x), tx = fmaxf(rr.y, cc.y);
            float by = fminf(rr.z, cc.z), bx2 = fminf(rr.w, cc.w);
            float wy = fmaxf(by - ty, 0.f), wx = fmaxf(bx2 - tx, 0.f);
            float inter = wy * wx;
            float areaj = (cc.z - cc.x) * (cc.w - cc.y);
            float iou = inter / (areai + areaj - inter + 1e-9f);
            if (iou > 0.7f) bits |= 1ull << c;
        }
    }
    g_mask[((size_t)b * PRE_NMS + i) * NW + cb] = bits;
}

// ---------------- NMS reduction v5 + fused finalize ----------------
__global__ void __launch_bounds__(512)
nms_reduce_finalize_kernel(float* __restrict__ out)
{
    int b = blockIdx.x;
    int tid = threadIdx.x;
    __shared__ u64 diag[2][64];
    __shared__ u64 remv[NW];
    __shared__ u64 svalid[NW];
    __shared__ u64 kw[NW];
    __shared__ int klist[64];
    __shared__ int snk;
    GRID_DEP_SYNC();   // wait for nms_mask's g_mask
    for (int v = tid; v < NW; v += 512) {
        remv[v] = 0ull;
        svalid[v] = g_validb[b * NW + v];
    }
    if (tid < 64)
        diag[0][tid] = (tid < PRE_NMS) ? g_mask[((size_t)b * PRE_NMS + tid) * NW + 0] : 0ull;
    __syncthreads();

    for (int w = 0; w < NW; w++) {
        int buf = w & 1;
        u64 rv = 0ull;
        if (w + 1 < NW && tid < 64) {
            int i = (w + 1) * 64 + tid;
            if (i < PRE_NMS) rv = g_mask[((size_t)b * PRE_NMS + i) * NW + (w + 1)];
        }
        if (tid == 0) {
            u64 cur = svalid[w] & ~remv[w];
            u64 kp = 0ull;
            int nk = 0;
            while (cur) {
                int bit = __ffsll((long long)cur) - 1;
                kp |= (1ull << bit);
                klist[nk++] = w * 64 + bit;
                cur &= ~diag[buf][bit];
                cur &= ~(1ull << bit);
            }
            snk = nk;
            kw[w] = kp;
        }
        __syncthreads();
        if (w + 1 < NW && tid < 64) diag[buf ^ 1][tid] = rv;
        int nk = snk;
        if (nk > 0) {
            int nv = NW - 1 - w;
            int total = nk * nv;
            for (int e0 = tid; e0 < total; e0 += 4096) {
                u64 mv[8];
                int vv[8];
#pragma unroll
                for (int s2 = 0; s2 < 8; s2++) {
                    int e = e0 + s2 * 512;
                    mv[s2] = 0ull;
                    vv[s2] = w + 1;
                    if (e < total) {
                        int q = e / nv;
                        int v = w + 1 + (e - q * nv);
                        vv[s2] = v;
                        mv[s2] = g_mask[((size_t)b * PRE_NMS + klist[q]) * NW + v];
                    }
                }
#pragma unroll
                for (int s2 = 0; s2 < 8; s2++)
                    if (mv[s2]) atomicOr(&remv[vv[s2]], mv[s2]);
            }
        }
        __syncthreads();
    }

    // ---- fused finalize ----
    __shared__ u32 kscan[NW];
    __shared__ u32 ktot;
    __shared__ int sel[POST_NMS];
    if (tid == 0) {
        u32 r = 0;
        for (int w = 0; w < NW; w++) { kscan[w] = r; r += (u32)__popcll(kw[w]); }
        ktot = r;
    }
    __syncthreads();
    u32 ktot_l = ktot;
    for (int w = tid; w < NW; w += 512) {
        u64 bits = kw[w];
        u32 base = kscan[w];
        u64 t = bits;
        while (t) {
            int bit = __ffsll((long long)t) - 1;
            t &= t - 1;
            if (base < POST_NMS) sel[base] = w * 64 + bit;
            base++;
        }
        u64 lim = (w == NW - 1) ? ((1ull << 48) - 1ull) : ~0ull;  // 6000 = 93*64+48
        u64 nt = (~bits) & lim;
        while (nt) {
            int bit = __ffsll((long long)nt) - 1;
            nt &= nt - 1;
            int i = w * 64 + bit;
            u64 below = (bit == 0) ? 0ull : ((1ull << bit) - 1ull);
            u32 kept_before = kscan[w] + (u32)__popcll(bits & below);
            u32 slot = ktot_l + (u32)i - kept_before;
            if (slot < POST_NMS) sel[slot] = i;
        }
    }
    __syncthreads();
    for (int s2 = tid; s2 < POST_NMS; s2 += 512) {
        int i = sel[s2];
        int v = (int)((kw[i >> 6] >> (i & 63)) & 1ull);
        float4 bx = v ? g_nmsbox[(size_t)b * PRE_NMS + i] : make_float4(0.f, 0.f, 0.f, 0.f);
        size_t ro = OFF_ROIS + (size_t)b * POST_NMS * 4 + (size_t)s2 * 4;
        out[ro + 0] = bx.x; out[ro + 1] = bx.y; out[ro + 2] = bx.z; out[ro + 3] = bx.w;
        out[OFF_RIDX + (size_t)b * POST_NMS + s2] = (float)b;
        out[OFF_RVALID + (size_t)b * POST_NMS + s2] = (float)v;
    }
}

// ---------------- launch helpers (PDL) ----------------
template <typename... Args>
static void launch_pdl(void (*kern)(Args...), dim3 grid, dim3 block, size_t smem,
                       bool pdl, Args... args)
{
    cudaLaunchConfig_t cfg = {};
    cfg.gridDim = grid;
    cfg.blockDim = block;
    cfg.dynamicSmemBytes = smem;
    cfg.stream = 0;
    cudaLaunchAttribute attr[1];
    if (pdl) {
        attr[0].id = cudaLaunchAttributeProgrammaticStreamSerialization;
        attr[0].val.programmaticStreamSerializationAllowed = 1;
        cfg.attrs = attr;
        cfg.numAttrs = 1;
    }
    cudaLaunchKernelEx(&cfg, kern, args...);
}

// ---------------- launch ----------------
extern "C" void kernel_launch(void* const* d_in, const int* in_sizes, int n_in,
                              void* d_out, int out_size)
{
    const float* feat   = (const float*)d_in[0];
    const float* convw  = (const float*)d_in[1];
    const float* convb  = (const float*)d_in[2];
    const float* scorew = (const float*)d_in[3];
    const float* scoreb = (const float*)d_in[4];
    const float* locw   = (const float*)d_in[5];
    const float* locb   = (const float*)d_in[6];
    float* out = (float*)d_out;

    cudaFuncSetAttribute(merge_gather_kernel, cudaFuncAttributeMaxDynamicSharedMemorySize, 65536);

    launch_pdl(init_kernel, dim3((2 * NCH * QPAD + 255) / 256), dim3(256), 0, false, feat, out);
    launch_pdl(conv3x3_kernel, dim3(32, 4, 2), dim3(256), 0, true, convw, convb);
    launch_pdl(gemm1x1_kernel, dim3(40, 5, 2), dim3(256), 0, true, scorew, scoreb, locw, locb);
    launch_pdl(decode_kernel, dim3((2 * NANCH + 255) / 256), dim3(256), 0, true, out);
    launch_pdl(scan_kernel, dim3(2), dim3(1024), 0, true, 0);
    launch_pdl(hist_kernel, dim3((2 * NANCH + 255) / 256), dim3(256), 0, true);
    launch_pdl(scan_kernel, dim3(2), dim3(1024), 0, true, 1);
    launch_pdl(compact_kernel, dim3((2 * NANCH + 255) / 256), dim3(256), 0, true);
    launch_pdl(local_sort_kernel, dim3(8, 2), dim3(1024), 0, true);
    launch_pdl(merge_gather_kernel, dim3(2), dim3(1024), 65536, true);
    launch_pdl(nms_mask_kernel, dim3(NTRI, 2), dim3(64), 0, true);
    launch_pdl(nms_reduce_finalize_kernel, dim3(2), dim3(512), 0, true, out);
}